// round 13
// baseline (speedup 1.0000x reference)
#include <cuda_runtime.h>
#include <cuda_bf16.h>
#include <cuda_fp16.h>
#include <math.h>
#include <stdint.h>
#include <stddef.h>

#define B_   2
#define T_   2048
#define NHQ  16
#define NKV  8
#define HD   128
#define FEAT 2048
#define WIN  1024
#define M_   (B_*T_)   // 4096
#define KDIM 2048
#define LOG2E 1.4426950408889634f

// ---------------- device scratch ----------------
__device__ __align__(128) float g_q  [(size_t)M_*NHQ*HD];
__device__ __align__(128) float g_k  [(size_t)M_*NKV*HD];

__device__ __align__(128) __half g_qhi[(size_t)M_*NHQ*HD];
__device__ __align__(128) __half g_qlo[(size_t)M_*NHQ*HD];
__device__ __align__(128) __half g_khi[(size_t)M_*NKV*HD];
__device__ __align__(128) __half g_klo[(size_t)M_*NKV*HD];
__device__ __align__(128) __half g_vhi[(size_t)M_*NKV*HD];

__device__ __align__(128) __half g_xhi  [(size_t)M_*KDIM];
__device__ __align__(128) __half g_enchi[(size_t)M_*KDIM];
__device__ __align__(128) __half g_wallhi[(size_t)4096*KDIM];
__device__ __align__(128) __half g_wothi [(size_t)2048*KDIM];

// ---------------- helpers ----------------
__device__ __forceinline__ uint32_t smem_u32(const void* p) {
    uint32_t a;
    asm("{ .reg .u64 t; cvta.to.shared.u64 t, %1; cvt.u32.u64 %0, t; }" : "=r"(a) : "l"(p));
    return a;
}
__device__ __forceinline__ void ldmx4(uint32_t& r0, uint32_t& r1, uint32_t& r2, uint32_t& r3, uint32_t addr) {
    asm volatile("ldmatrix.sync.aligned.m8n8.x4.shared.b16 {%0,%1,%2,%3}, [%4];"
                 : "=r"(r0), "=r"(r1), "=r"(r2), "=r"(r3) : "r"(addr));
}
__device__ __forceinline__ void ldmx4t(uint32_t& r0, uint32_t& r1, uint32_t& r2, uint32_t& r3, uint32_t addr) {
    asm volatile("ldmatrix.sync.aligned.m8n8.x4.trans.shared.b16 {%0,%1,%2,%3}, [%4];"
                 : "=r"(r0), "=r"(r1), "=r"(r2), "=r"(r3) : "r"(addr));
}
__device__ __forceinline__ void mma16816h(float* c, const uint32_t* a, const uint32_t* b) {
    asm volatile("mma.sync.aligned.m16n8k16.row.col.f32.f16.f16.f32 "
                 "{%0,%1,%2,%3}, {%4,%5,%6,%7}, {%8,%9}, {%0,%1,%2,%3};"
                 : "+f"(c[0]), "+f"(c[1]), "+f"(c[2]), "+f"(c[3])
                 : "r"(a[0]), "r"(a[1]), "r"(a[2]), "r"(a[3]), "r"(b[0]), "r"(b[1]));
}
#define CP_ASYNC16(dst, src) \
    asm volatile("cp.async.cg.shared.global [%0], [%1], 16;" :: "r"(dst), "l"(src))
#define CP_COMMIT() asm volatile("cp.async.commit_group;" ::: "memory")
#define CP_WAIT(n)  asm volatile("cp.async.wait_group %0;" :: "n"(n) : "memory")

__device__ __forceinline__ float fastexp2(float x) {
    x = fmaxf(x, -120.f);
    int ei = __float2int_rn(x);
    float f = x - (float)ei;
    float p = 1.f + f*(0.6931472f + f*(0.24022651f + f*(0.05550411f + f*(0.00961813f + f*0.00133336f))));
    return p * __int_as_float((ei + 127) << 23);
}

// ---------------- fp32 -> fp16 hi-lo split ----------------
__device__ __forceinline__ void split2h(float v, unsigned short& h, unsigned short& l) {
    __half hh = __float2half_rn(v);
    float r = v - __half2float(hh);
    __half hl = __float2half_rn(r);
    h = *reinterpret_cast<unsigned short*>(&hh);
    l = *reinterpret_cast<unsigned short*>(&hl);
}

__global__ void convert_x_kernel(const float* __restrict__ src) {
    int i = blockIdx.x*blockDim.x + threadIdx.x;
    float4 v = ((const float4*)src)[i];
    __half2 a = __floats2half2_rn(v.x, v.y);
    __half2 b = __floats2half2_rn(v.z, v.w);
    uint2 o = { *(uint32_t*)&a, *(uint32_t*)&b };
    ((uint2*)g_xhi)[i] = o;
}

__global__ void wqkv_transpose_kernel(const float* __restrict__ wq, const float* __restrict__ wkv) {
    __shared__ float t[32][33];
    int head = blockIdx.z;
    const float* src = (head < 16) ? (wq + (size_t)head*KDIM*HD)
                                   : (wkv + (size_t)(head-16)*KDIM*HD);
    int hd0 = blockIdx.x*32, k0 = blockIdx.y*32;
    int tx = threadIdx.x, ty = threadIdx.y;
    #pragma unroll
    for (int i = 0; i < 32; i += 8)
        t[ty+i][tx] = src[(size_t)(k0+ty+i)*HD + hd0 + tx];
    __syncthreads();
    #pragma unroll
    for (int i = 0; i < 32; i += 8) {
        int n = head*128 + hd0 + ty + i;
        g_wallhi[(size_t)n*KDIM + k0 + tx] = __float2half_rn(t[tx][ty+i]);
    }
}
__global__ void wo_transpose_kernel(const float* __restrict__ wo) {
    __shared__ float t[32][33];
    int c0 = blockIdx.x*32, r0 = blockIdx.y*32;
    int tx = threadIdx.x, ty = threadIdx.y;
    #pragma unroll
    for (int i = 0; i < 32; i += 8)
        t[ty+i][tx] = wo[(size_t)(r0+ty+i)*2048 + c0 + tx];
    __syncthreads();
    #pragma unroll
    for (int i = 0; i < 32; i += 8) {
        int n = c0 + ty + i;
        g_wothi[(size_t)n*KDIM + r0 + tx] = __float2half_rn(t[tx][ty+i]);
    }
}

// ---------------- mma.sync fp16 GEMM (frozen from R12) ----------------
#define KC      32
#define NKITER  (KDIM/KC)
#define AROWB   80
#define BUF_T   (128*AROWB)
#define STAGEB  (2*BUF_T)
#define GEMM_SMEM (3*STAGEB)    // 61440

__global__ __launch_bounds__(256, 2) void gemm_mma_kernel(float* __restrict__ outp, int mode) {
    extern __shared__ char smx[];
    uint32_t sbase = smem_u32(smx);
    int tid = threadIdx.x, wid = tid >> 5, lane = tid & 31;
    int bn = blockIdx.x, bm = blockIdx.y;
    int m0 = bm*128, n0 = bn*128;

    const __half *Ahi, *Bhi;
    if (mode == 0) { Ahi = g_xhi;   Bhi = g_wallhi; }
    else           { Ahi = g_enchi; Bhi = g_wothi;  }
    const __half* src0 = Ahi + (size_t)m0*KDIM;
    const __half* src2 = Bhi + (size_t)n0*KDIM;

    int wm = (wid & 3) * 32;
    int wn = (wid >> 2) * 64;

    uint32_t aoff = (uint32_t)((lane & 15)*AROWB + (lane >> 4)*16);
    int g = lane >> 3;
    uint32_t boff = (uint32_t)(((lane & 7) + (g >> 1)*8)*AROWB + (g & 1)*16);

    float acc[2][8][4];
    #pragma unroll
    for (int mt = 0; mt < 2; mt++)
        #pragma unroll
        for (int nt = 0; nt < 8; nt++)
            #pragma unroll
            for (int c = 0; c < 4; c++) acc[mt][nt][c] = 0.f;

    #define LOAD_STAGE(s, k0) do { \
        _Pragma("unroll") \
        for (int r = 0; r < 4; r++) { \
            const __half* sp_ = (r < 2) ? src0 : src2; \
            int within = (r & 1)*256 + tid; \
            int row = within >> 2, c16 = within & 3; \
            const void* sp = sp_ + (size_t)row*KDIM + (k0) + c16*8; \
            uint32_t dp = sbase + (s)*STAGEB + (r >> 1)*BUF_T + row*AROWB + c16*16; \
            CP_ASYNC16(dp, sp); \
        } \
        CP_COMMIT(); \
    } while (0)

    LOAD_STAGE(0, 0);
    LOAD_STAGE(1, KC);

    int p = 0, pn = 2;
    for (int i = 0; i < NKITER; i++) {
        if (i < NKITER-1) { CP_WAIT(1); } else { CP_WAIT(0); }
        __syncthreads();
        if (i + 2 < NKITER) {
            LOAD_STAGE(pn, (i+2)*KC);
            if (++pn == 3) pn = 0;
        }

        uint32_t saA = sbase + p*STAGEB;
        uint32_t saB = saA + BUF_T;
        if (++p == 3) p = 0;

        #pragma unroll
        for (int kstep = 0; kstep < 2; kstep++) {
            uint32_t koff = kstep*32;
            uint32_t ah[2][4], bb[8][2];
            #pragma unroll
            for (int mt = 0; mt < 2; mt++)
                ldmx4(ah[mt][0], ah[mt][1], ah[mt][2], ah[mt][3],
                      saA + aoff + (wm + mt*16)*AROWB + koff);
            #pragma unroll
            for (int ntp = 0; ntp < 4; ntp++)
                ldmx4(bb[2*ntp][0], bb[2*ntp][1], bb[2*ntp+1][0], bb[2*ntp+1][1],
                      saB + boff + (wn + ntp*16)*AROWB + koff);
            #pragma unroll
            for (int nt = 0; nt < 8; nt++)
                #pragma unroll
                for (int mt = 0; mt < 2; mt++)
                    mma16816h(acc[mt][nt], ah[mt], bb[nt]);
        }
    }

    int rbase_r = wm + (lane >> 2);
    int cloc = wn + (lane & 3)*2;

    if (mode == 0 && bn >= 24) {
        int coloff = (bn-24)*128;
        #pragma unroll
        for (int mt = 0; mt < 2; mt++) {
            #pragma unroll
            for (int nt = 0; nt < 8; nt++) {
                size_t r0 = (size_t)(m0 + rbase_r + mt*16)*(NKV*HD) + coloff + cloc + nt*8;
                size_t r1 = r0 + 8*(size_t)(NKV*HD);
                __half2 h0 = __floats2half2_rn(acc[mt][nt][0], acc[mt][nt][1]);
                __half2 h1 = __floats2half2_rn(acc[mt][nt][2], acc[mt][nt][3]);
                *(__half2*)(g_vhi + r0) = h0;
                *(__half2*)(g_vhi + r1) = h1;
            }
        }
    } else {
        float* dst; int ldd, coloff;
        if (mode == 0) {
            if (bn < 16) { dst = g_q; ldd = NHQ*HD; coloff = bn*128; }
            else         { dst = g_k; ldd = NKV*HD; coloff = (bn-16)*128; }
        } else { dst = outp; ldd = FEAT; coloff = bn*128; }
        int rbase = m0 + rbase_r;
        int cbase = coloff + cloc;
        #pragma unroll
        for (int mt = 0; mt < 2; mt++) {
            #pragma unroll
            for (int nt = 0; nt < 8; nt++) {
                size_t r0 = (size_t)(rbase + mt*16)*ldd + cbase + nt*8;
                *(float2*)&dst[r0]                 = make_float2(acc[mt][nt][0], acc[mt][nt][1]);
                *(float2*)&dst[r0 + 8*(size_t)ldd] = make_float2(acc[mt][nt][2], acc[mt][nt][3]);
            }
        }
    }
}

// ---------------- RoPE -> fp16 hi/lo ----------------
__global__ void rope_kernel(int is_q) {
    int nh = is_q ? NHQ : NKV;
    int idx = blockIdx.x*blockDim.x + threadIdx.x;
    if (idx >= M_*nh*64) return;
    const float* p = is_q ? g_q : g_k;
    __half* dhi = is_q ? g_qhi : g_khi;
    __half* dlo = is_q ? g_qlo : g_klo;
    float scale = is_q ? 0.08838834764831845f : 1.0f;

    int h  = idx & 63;
    int n  = (idx >> 6) % nh;
    int bt = idx / (64*nh);
    int t  = bt & (T_-1);

    size_t base = ((size_t)bt*nh + n)*HD;
    float inv = exp2f(-(float)h * (13.287712379549449f / 64.0f));
    float ang = (float)t * inv;
    float sv, cv;
    sincosf(ang, &sv, &cv);
    float f = p[base + h], s2 = p[base + h + 64];
    float v1 = (f*cv - s2*sv) * scale;
    float v2 = (s2*cv + f*sv) * scale;
    unsigned short h1, l1, h2, l2;
    split2h(v1, h1, l1); split2h(v2, h2, l2);
    ((unsigned short*)dhi)[base + h]      = h1;
    ((unsigned short*)dlo)[base + h]      = l1;
    ((unsigned short*)dhi)[base + h + 64] = h2;
    ((unsigned short*)dlo)[base + h + 64] = l2;
}

// ---------------- flash attention: reg-Q, double-buffered K & V, 1 sync/tile ----------------
#define FROW 272
#define PROW 144
#define FK0H 0
#define FK1H (2*64*FROW)        // KL always at KH + 64*FROW
#define FKLD (64*FROW)
#define FV0  (4*64*FROW)        // 69632
#define FV1  (5*64*FROW)        // 87040
#define FPP  (6*64*FROW)        // 104448
#define FLASH_SMEM (FPP + 64*PROW)  // 113664 -> 2 CTAs/SM (227328 <= 228KB)

__global__ __launch_bounds__(128, 2) void flash_mma_kernel() {
    extern __shared__ char fsm[];
    uint32_t sb = smem_u32(fsm);
    int tid = threadIdx.x, w = tid >> 5, lane = tid & 31;
    int qt = blockIdx.x, head = blockIdx.y, b = blockIdx.z;
    int q0 = qt*64;
    int kvh = head >> 1;

    const __half* kh_b = g_khi + ((size_t)(b*T_))*NKV*HD + (size_t)kvh*HD;
    const __half* kl_b = g_klo + ((size_t)(b*T_))*NKV*HD + (size_t)kvh*HD;
    const __half* vh_b = g_vhi + ((size_t)(b*T_))*NKV*HD + (size_t)kvh*HD;

    int s_lo_raw = q0 - (WIN - 1);
    int s_lo = (s_lo_raw < 0 ? 0 : s_lo_raw) & ~63;
    int niter = ((q0 - s_lo) >> 6) + 1;

    uint32_t aoffQ = (uint32_t)((w*16 + (lane & 15))*FROW + (lane >> 4)*16);
    uint32_t brow  = (uint32_t)((lane & 7) + ((lane >> 4))*8);
    uint32_t bbyte = (uint32_t)(((lane >> 3) & 1)*16);
    uint32_t vrow  = (uint32_t)((lane & 7) + ((lane >> 3) & 1)*8);
    uint32_t vbyte = (uint32_t)((lane >> 4)*16);
    uint32_t aoffP = (uint32_t)((w*16 + (lane & 15))*PROW + (lane >> 4)*16);

    // ---- stage Q through K-buffer 0, load to registers ----
    {
        const __half* qh = g_qhi + ((size_t)(b*T_ + q0)*NHQ + head)*HD;
        const __half* ql = g_qlo + ((size_t)(b*T_ + q0)*NHQ + head)*HD;
        #pragma unroll
        for (int i = 0; i < 8; i++) {
            int idx = i*128 + tid;
            int row = idx >> 4, c = idx & 15;
            CP_ASYNC16(sb + FK0H + row*FROW + c*16,        qh + (size_t)row*(NHQ*HD) + c*8);
            CP_ASYNC16(sb + FK0H + FKLD + row*FROW + c*16, ql + (size_t)row*(NHQ*HD) + c*8);
        }
        CP_COMMIT();
        CP_WAIT(0);
        __syncthreads();
    }
    uint32_t qh_r[8][4], ql_r[8][4];
    #pragma unroll
    for (int kstep = 0; kstep < 8; kstep++) {
        ldmx4(qh_r[kstep][0], qh_r[kstep][1], qh_r[kstep][2], qh_r[kstep][3],
              sb + FK0H + aoffQ + kstep*32);
        ldmx4(ql_r[kstep][0], ql_r[kstep][1], ql_r[kstep][2], ql_r[kstep][3],
              sb + FK0H + FKLD + aoffQ + kstep*32);
    }
    __syncthreads();   // all Q reads done before K0 overwrites buffer 0

    // ---- issue K0 + V0 ----
    #pragma unroll
    for (int i = 0; i < 8; i++) {
        int idx = i*128 + tid;
        int row = idx >> 4, c = idx & 15;
        CP_ASYNC16(sb + FK0H + row*FROW + c*16,        kh_b + (size_t)(s_lo+row)*(NKV*HD) + c*8);
        CP_ASYNC16(sb + FK0H + FKLD + row*FROW + c*16, kl_b + (size_t)(s_lo+row)*(NKV*HD) + c*8);
        CP_ASYNC16(sb + FV0 + row*FROW + c*16,         vh_b + (size_t)(s_lo+row)*(NKV*HD) + c*8);
    }
    CP_COMMIT();

    float m0 = -1e30f, m1 = -1e30f, l0 = 0.f, l1 = 0.f;
    float o[16][4];
    #pragma unroll
    for (int nt = 0; nt < 16; nt++)
        #pragma unroll
        for (int c = 0; c < 4; c++) o[nt][c] = 0.f;

    int q_r0 = q0 + w*16 + (lane >> 2);
    int q_r1 = q_r0 + 8;

    for (int it = 0; it < niter; it++) {
        int ks = s_lo + it*64;
        uint32_t kb = sb + ((it & 1) ? FK1H : FK0H);
        uint32_t vbf = sb + ((it & 1) ? FV1 : FV0);

        CP_WAIT(0);          // K_it + V_it complete
        __syncthreads();     // visible to all; prior readers of the other buffers done

        if (it + 1 < niter) {
            uint32_t kbn = sb + (((it+1) & 1) ? FK1H : FK0H);
            uint32_t vbn = sb + (((it+1) & 1) ? FV1 : FV0);
            int ksn = ks + 64;
            #pragma unroll
            for (int i = 0; i < 8; i++) {
                int idx = i*128 + tid;
                int row = idx >> 4, c = idx & 15;
                CP_ASYNC16(kbn + row*FROW + c*16,        kh_b + (size_t)(ksn+row)*(NKV*HD) + c*8);
                CP_ASYNC16(kbn + FKLD + row*FROW + c*16, kl_b + (size_t)(ksn+row)*(NKV*HD) + c*8);
                CP_ASYNC16(vbn + row*FROW + c*16,        vh_b + (size_t)(ksn+row)*(NKV*HD) + c*8);
            }
            CP_COMMIT();
        }

        // ---- S = Q @ K^T (reg Q) ----
        float sc[8][4];
        #pragma unroll
        for (int nt = 0; nt < 8; nt++)
            #pragma unroll
            for (int c = 0; c < 4; c++) sc[nt][c] = 0.f;

        #pragma unroll
        for (int kstep = 0; kstep < 8; kstep++) {
            uint32_t koff = kstep*32;
            uint32_t bh[2][2];
            #pragma unroll
            for (int ntp = 0; ntp < 4; ntp++) {
                uint32_t kaddr = kb + (brow + ntp*16)*FROW + bbyte + koff;
                ldmx4(bh[0][0], bh[0][1], bh[1][0], bh[1][1], kaddr);
                mma16816h(sc[2*ntp],   qh_r[kstep], bh[0]);
                mma16816h(sc[2*ntp],   ql_r[kstep], bh[0]);
                mma16816h(sc[2*ntp+1], qh_r[kstep], bh[1]);
                mma16816h(sc[2*ntp+1], ql_r[kstep], bh[1]);
                ldmx4(bh[0][0], bh[0][1], bh[1][0], bh[1][1], kaddr + FKLD);
                mma16816h(sc[2*ntp],   qh_r[kstep], bh[0]);
                mma16816h(sc[2*ntp+1], qh_r[kstep], bh[1]);
            }
        }

        // ---- soft-cap, mask, online softmax (no syncs; P is warp-private) ----
        float mx0 = -1e30f, mx1 = -1e30f;
        #pragma unroll
        for (int nt = 0; nt < 8; nt++) {
            #pragma unroll
            for (int c = 0; c < 4; c++) {
                float s = sc[nt][c];
                float u = s * 0.02f;
                float t2 = u*u;
                float pl = 1.f + t2*(-0.33333334f + t2*(0.13333333f + t2*(-0.05396825f + t2*0.02186949f)));
                float sp = s * pl;
                int col = ks + nt*8 + (lane & 3)*2 + (c & 1);
                int qq = (c < 2) ? q_r0 : q_r1;
                bool valid = (col <= qq) && (col > qq - WIN);
                sp = valid ? sp : -1e30f;
                sc[nt][c] = sp;
                if (c < 2) mx0 = fmaxf(mx0, sp); else mx1 = fmaxf(mx1, sp);
            }
        }
        mx0 = fmaxf(mx0, __shfl_xor_sync(0xffffffffu, mx0, 1));
        mx0 = fmaxf(mx0, __shfl_xor_sync(0xffffffffu, mx0, 2));
        mx1 = fmaxf(mx1, __shfl_xor_sync(0xffffffffu, mx1, 1));
        mx1 = fmaxf(mx1, __shfl_xor_sync(0xffffffffu, mx1, 2));

        float mn0 = fmaxf(fmaxf(m0, mx0), -60.f);
        float mn1 = fmaxf(fmaxf(m1, mx1), -60.f);
        float a0 = fastexp2((m0 - mn0)*LOG2E);
        float a1 = fastexp2((m1 - mn1)*LOG2E);
        m0 = mn0; m1 = mn1;

        float ps0 = 0.f, ps1 = 0.f;
        int prow0 = w*16 + (lane >> 2);
        uint32_t pcolb = (uint32_t)((lane & 3)*4);
        #pragma unroll
        for (int nt = 0; nt < 8; nt++) {
            float p0 = fastexp2((sc[nt][0] - mn0)*LOG2E);
            float p1 = fastexp2((sc[nt][1] - mn0)*LOG2E);
            float p2 = fastexp2((sc[nt][2] - mn1)*LOG2E);
            float p3 = fastexp2((sc[nt][3] - mn1)*LOG2E);
            ps0 += p0 + p1; ps1 += p2 + p3;
            __half2 lo2 = __floats2half2_rn(p0, p1);
            __half2 hi2 = __floats2half2_rn(p2, p3);
            *(uint32_t*)(fsm + FPP + prow0*PROW + nt*16 + pcolb)     = *(uint32_t*)&lo2;
            *(uint32_t*)(fsm + FPP + (prow0+8)*PROW + nt*16 + pcolb) = *(uint32_t*)&hi2;
        }
        ps0 += __shfl_xor_sync(0xffffffffu, ps0, 1);
        ps0 += __shfl_xor_sync(0xffffffffu, ps0, 2);
        ps1 += __shfl_xor_sync(0xffffffffu, ps1, 1);
        ps1 += __shfl_xor_sync(0xffffffffu, ps1, 2);
        l0 = l0*a0 + ps0;
        l1 = l1*a1 + ps1;
        #pragma unroll
        for (int nt = 0; nt < 16; nt++) {
            o[nt][0] *= a0; o[nt][1] *= a0;
            o[nt][2] *= a1; o[nt][3] *= a1;
        }
        __syncwarp();   // P stores visible within warp before ldmatrix

        // ---- O += P @ V ----
        #pragma unroll
        for (int kstep = 0; kstep < 4; kstep++) {
            uint32_t ap[4];
            ldmx4(ap[0], ap[1], ap[2], ap[3], sb + FPP + aoffP + kstep*32);
            #pragma unroll
            for (int nth = 0; nth < 8; nth++) {
                uint32_t vb[2][2];
                uint32_t va = vbf + (vrow + kstep*16)*FROW + nth*32 + vbyte;
                ldmx4t(vb[0][0], vb[0][1], vb[1][0], vb[1][1], va);
                mma16816h(o[2*nth],   ap, vb[0]);
                mma16816h(o[2*nth+1], ap, vb[1]);
            }
        }
    }

    // ---- normalize, store encoded (fp16) ----
    float li0 = 1.f / l0, li1 = 1.f / l1;
    size_t enc_r0 = ((size_t)(b*T_ + q_r0)*NHQ + head)*HD;
    size_t enc_r1 = ((size_t)(b*T_ + q_r1)*NHQ + head)*HD;
    int cb = (lane & 3)*2;
    #pragma unroll
    for (int nt = 0; nt < 16; nt++) {
        __half2 h0 = __floats2half2_rn(o[nt][0]*li0, o[nt][1]*li0);
        __half2 h1 = __floats2half2_rn(o[nt][2]*li1, o[nt][3]*li1);
        *(__half2*)(g_enchi + enc_r0 + nt*8 + cb) = h0;
        *(__half2*)(g_enchi + enc_r1 + nt*8 + cb) = h1;
    }
}

// ---------------------------------------------------------------------------
extern "C" void kernel_launch(void* const* d_in, const int* in_sizes, int n_in,
                              void* d_out, int out_size) {
    const float* x   = (const float*)d_in[0];
    const float* wq  = (const float*)d_in[3];
    const float* wkv = (const float*)d_in[4];
    const float* wo  = (const float*)d_in[5];
    float* out = (float*)d_out;

    cudaFuncSetAttribute(flash_mma_kernel, cudaFuncAttributeMaxDynamicSharedMemorySize, FLASH_SMEM);
    cudaFuncSetAttribute(gemm_mma_kernel,  cudaFuncAttributeMaxDynamicSharedMemorySize, GEMM_SMEM);

    convert_x_kernel<<<(M_*KDIM/4)/256, 256>>>(x);
    wqkv_transpose_kernel<<<dim3(4, 64, 32), dim3(32, 8)>>>(wq, wkv);
    wo_transpose_kernel<<<dim3(64, 64), dim3(32, 8)>>>(wo);

    gemm_mma_kernel<<<dim3(32, 32), 256, GEMM_SMEM>>>(nullptr, 0);   // QKV (+fused V fp16)

    rope_kernel<<<(M_*NHQ*64 + 255)/256, 256>>>(1);
    rope_kernel<<<(M_*NKV*64 + 255)/256, 256>>>(0);

    flash_mma_kernel<<<dim3(T_/64, NHQ, B_), 128, FLASH_SMEM>>>();

    gemm_mma_kernel<<<dim3(16, 32), 256, GEMM_SMEM>>>(out, 1);       // out proj
}

// round 14
// speedup vs baseline: 1.0777x; 1.0777x over previous
#include <cuda_runtime.h>
#include <cuda_bf16.h>
#include <cuda_fp16.h>
#include <math.h>
#include <stdint.h>
#include <stddef.h>

#define B_   2
#define T_   2048
#define NHQ  16
#define NKV  8
#define HD   128
#define FEAT 2048
#define WIN  1024
#define M_   (B_*T_)   // 4096
#define KDIM 2048
#define LOG2E 1.4426950408889634f

// ---------------- device scratch ----------------
__device__ __align__(128) float g_q  [(size_t)M_*NHQ*HD];
__device__ __align__(128) float g_k  [(size_t)M_*NKV*HD];

__device__ __align__(128) __half g_qhi[(size_t)M_*NHQ*HD];
__device__ __align__(128) __half g_qlo[(size_t)M_*NHQ*HD];
__device__ __align__(128) __half g_khi[(size_t)M_*NKV*HD];
__device__ __align__(128) __half g_vhi[(size_t)M_*NKV*HD];

__device__ __align__(128) __half g_xhi  [(size_t)M_*KDIM];
__device__ __align__(128) __half g_enchi[(size_t)M_*KDIM];
__device__ __align__(128) __half g_wallhi[(size_t)4096*KDIM];
__device__ __align__(128) __half g_wothi [(size_t)2048*KDIM];

// ---------------- helpers ----------------
__device__ __forceinline__ uint32_t smem_u32(const void* p) {
    uint32_t a;
    asm("{ .reg .u64 t; cvta.to.shared.u64 t, %1; cvt.u32.u64 %0, t; }" : "=r"(a) : "l"(p));
    return a;
}
__device__ __forceinline__ void ldmx4(uint32_t& r0, uint32_t& r1, uint32_t& r2, uint32_t& r3, uint32_t addr) {
    asm volatile("ldmatrix.sync.aligned.m8n8.x4.shared.b16 {%0,%1,%2,%3}, [%4];"
                 : "=r"(r0), "=r"(r1), "=r"(r2), "=r"(r3) : "r"(addr));
}
__device__ __forceinline__ void ldmx4t(uint32_t& r0, uint32_t& r1, uint32_t& r2, uint32_t& r3, uint32_t addr) {
    asm volatile("ldmatrix.sync.aligned.m8n8.x4.trans.shared.b16 {%0,%1,%2,%3}, [%4];"
                 : "=r"(r0), "=r"(r1), "=r"(r2), "=r"(r3) : "r"(addr));
}
__device__ __forceinline__ void mma16816h(float* c, const uint32_t* a, const uint32_t* b) {
    asm volatile("mma.sync.aligned.m16n8k16.row.col.f32.f16.f16.f32 "
                 "{%0,%1,%2,%3}, {%4,%5,%6,%7}, {%8,%9}, {%0,%1,%2,%3};"
                 : "+f"(c[0]), "+f"(c[1]), "+f"(c[2]), "+f"(c[3])
                 : "r"(a[0]), "r"(a[1]), "r"(a[2]), "r"(a[3]), "r"(b[0]), "r"(b[1]));
}
#define CP_ASYNC16(dst, src) \
    asm volatile("cp.async.cg.shared.global [%0], [%1], 16;" :: "r"(dst), "l"(src))
#define CP_COMMIT() asm volatile("cp.async.commit_group;" ::: "memory")
#define CP_WAIT(n)  asm volatile("cp.async.wait_group %0;" :: "n"(n) : "memory")

__device__ __forceinline__ float fastexp2(float x) {
    x = fmaxf(x, -120.f);
    int ei = __float2int_rn(x);
    float f = x - (float)ei;
    float p = 1.f + f*(0.6931472f + f*(0.24022651f + f*(0.05550411f + f*(0.00961813f + f*0.00133336f))));
    return p * __int_as_float((ei + 127) << 23);
}

// ---------------- fp32 -> fp16 hi-lo split ----------------
__device__ __forceinline__ void split2h(float v, unsigned short& h, unsigned short& l) {
    __half hh = __float2half_rn(v);
    float r = v - __half2float(hh);
    __half hl = __float2half_rn(r);
    h = *reinterpret_cast<unsigned short*>(&hh);
    l = *reinterpret_cast<unsigned short*>(&hl);
}

__global__ void convert_x_kernel(const float* __restrict__ src) {
    int i = blockIdx.x*blockDim.x + threadIdx.x;
    float4 v = ((const float4*)src)[i];
    __half2 a = __floats2half2_rn(v.x, v.y);
    __half2 b = __floats2half2_rn(v.z, v.w);
    uint2 o = { *(uint32_t*)&a, *(uint32_t*)&b };
    ((uint2*)g_xhi)[i] = o;
}

__global__ void wqkv_transpose_kernel(const float* __restrict__ wq, const float* __restrict__ wkv) {
    __shared__ float t[32][33];
    int head = blockIdx.z;
    const float* src = (head < 16) ? (wq + (size_t)head*KDIM*HD)
                                   : (wkv + (size_t)(head-16)*KDIM*HD);
    int hd0 = blockIdx.x*32, k0 = blockIdx.y*32;
    int tx = threadIdx.x, ty = threadIdx.y;
    #pragma unroll
    for (int i = 0; i < 32; i += 8)
        t[ty+i][tx] = src[(size_t)(k0+ty+i)*HD + hd0 + tx];
    __syncthreads();
    #pragma unroll
    for (int i = 0; i < 32; i += 8) {
        int n = head*128 + hd0 + ty + i;
        g_wallhi[(size_t)n*KDIM + k0 + tx] = __float2half_rn(t[tx][ty+i]);
    }
}
__global__ void wo_transpose_kernel(const float* __restrict__ wo) {
    __shared__ float t[32][33];
    int c0 = blockIdx.x*32, r0 = blockIdx.y*32;
    int tx = threadIdx.x, ty = threadIdx.y;
    #pragma unroll
    for (int i = 0; i < 32; i += 8)
        t[ty+i][tx] = wo[(size_t)(r0+ty+i)*2048 + c0 + tx];
    __syncthreads();
    #pragma unroll
    for (int i = 0; i < 32; i += 8) {
        int n = c0 + ty + i;
        g_wothi[(size_t)n*KDIM + r0 + tx] = __float2half_rn(t[tx][ty+i]);
    }
}

// ---------------- mma.sync fp16 GEMM (frozen from R12) ----------------
#define KC      32
#define NKITER  (KDIM/KC)
#define AROWB   80
#define BUF_T   (128*AROWB)
#define STAGEB  (2*BUF_T)
#define GEMM_SMEM (3*STAGEB)    // 61440

__global__ __launch_bounds__(256, 2) void gemm_mma_kernel(float* __restrict__ outp, int mode) {
    extern __shared__ char smx[];
    uint32_t sbase = smem_u32(smx);
    int tid = threadIdx.x, wid = tid >> 5, lane = tid & 31;
    int bn = blockIdx.x, bm = blockIdx.y;
    int m0 = bm*128, n0 = bn*128;

    const __half *Ahi, *Bhi;
    if (mode == 0) { Ahi = g_xhi;   Bhi = g_wallhi; }
    else           { Ahi = g_enchi; Bhi = g_wothi;  }
    const __half* src0 = Ahi + (size_t)m0*KDIM;
    const __half* src2 = Bhi + (size_t)n0*KDIM;

    int wm = (wid & 3) * 32;
    int wn = (wid >> 2) * 64;

    uint32_t aoff = (uint32_t)((lane & 15)*AROWB + (lane >> 4)*16);
    int g = lane >> 3;
    uint32_t boff = (uint32_t)(((lane & 7) + (g >> 1)*8)*AROWB + (g & 1)*16);

    float acc[2][8][4];
    #pragma unroll
    for (int mt = 0; mt < 2; mt++)
        #pragma unroll
        for (int nt = 0; nt < 8; nt++)
            #pragma unroll
            for (int c = 0; c < 4; c++) acc[mt][nt][c] = 0.f;

    #define LOAD_STAGE(s, k0) do { \
        _Pragma("unroll") \
        for (int r = 0; r < 4; r++) { \
            const __half* sp_ = (r < 2) ? src0 : src2; \
            int within = (r & 1)*256 + tid; \
            int row = within >> 2, c16 = within & 3; \
            const void* sp = sp_ + (size_t)row*KDIM + (k0) + c16*8; \
            uint32_t dp = sbase + (s)*STAGEB + (r >> 1)*BUF_T + row*AROWB + c16*16; \
            CP_ASYNC16(dp, sp); \
        } \
        CP_COMMIT(); \
    } while (0)

    LOAD_STAGE(0, 0);
    LOAD_STAGE(1, KC);

    int p = 0, pn = 2;
    for (int i = 0; i < NKITER; i++) {
        if (i < NKITER-1) { CP_WAIT(1); } else { CP_WAIT(0); }
        __syncthreads();
        if (i + 2 < NKITER) {
            LOAD_STAGE(pn, (i+2)*KC);
            if (++pn == 3) pn = 0;
        }

        uint32_t saA = sbase + p*STAGEB;
        uint32_t saB = saA + BUF_T;
        if (++p == 3) p = 0;

        #pragma unroll
        for (int kstep = 0; kstep < 2; kstep++) {
            uint32_t koff = kstep*32;
            uint32_t ah[2][4], bb[8][2];
            #pragma unroll
            for (int mt = 0; mt < 2; mt++)
                ldmx4(ah[mt][0], ah[mt][1], ah[mt][2], ah[mt][3],
                      saA + aoff + (wm + mt*16)*AROWB + koff);
            #pragma unroll
            for (int ntp = 0; ntp < 4; ntp++)
                ldmx4(bb[2*ntp][0], bb[2*ntp][1], bb[2*ntp+1][0], bb[2*ntp+1][1],
                      saB + boff + (wn + ntp*16)*AROWB + koff);
            #pragma unroll
            for (int nt = 0; nt < 8; nt++)
                #pragma unroll
                for (int mt = 0; mt < 2; mt++)
                    mma16816h(acc[mt][nt], ah[mt], bb[nt]);
        }
    }

    int rbase_r = wm + (lane >> 2);
    int cloc = wn + (lane & 3)*2;

    if (mode == 0 && bn >= 24) {
        int coloff = (bn-24)*128;
        #pragma unroll
        for (int mt = 0; mt < 2; mt++) {
            #pragma unroll
            for (int nt = 0; nt < 8; nt++) {
                size_t r0 = (size_t)(m0 + rbase_r + mt*16)*(NKV*HD) + coloff + cloc + nt*8;
                size_t r1 = r0 + 8*(size_t)(NKV*HD);
                __half2 h0 = __floats2half2_rn(acc[mt][nt][0], acc[mt][nt][1]);
                __half2 h1 = __floats2half2_rn(acc[mt][nt][2], acc[mt][nt][3]);
                *(__half2*)(g_vhi + r0) = h0;
                *(__half2*)(g_vhi + r1) = h1;
            }
        }
    } else {
        float* dst; int ldd, coloff;
        if (mode == 0) {
            if (bn < 16) { dst = g_q; ldd = NHQ*HD; coloff = bn*128; }
            else         { dst = g_k; ldd = NKV*HD; coloff = (bn-16)*128; }
        } else { dst = outp; ldd = FEAT; coloff = bn*128; }
        int rbase = m0 + rbase_r;
        int cbase = coloff + cloc;
        #pragma unroll
        for (int mt = 0; mt < 2; mt++) {
            #pragma unroll
            for (int nt = 0; nt < 8; nt++) {
                size_t r0 = (size_t)(rbase + mt*16)*ldd + cbase + nt*8;
                *(float2*)&dst[r0]                 = make_float2(acc[mt][nt][0], acc[mt][nt][1]);
                *(float2*)&dst[r0 + 8*(size_t)ldd] = make_float2(acc[mt][nt][2], acc[mt][nt][3]);
            }
        }
    }
}

// ---------------- RoPE: Q -> fp16 hi/lo, K -> fp16 hi only ----------------
__global__ void rope_kernel(int is_q) {
    int nh = is_q ? NHQ : NKV;
    int idx = blockIdx.x*blockDim.x + threadIdx.x;
    if (idx >= M_*nh*64) return;
    const float* p = is_q ? g_q : g_k;
    __half* dhi = is_q ? g_qhi : g_khi;
    float scale = is_q ? 0.08838834764831845f : 1.0f;

    int h  = idx & 63;
    int n  = (idx >> 6) % nh;
    int bt = idx / (64*nh);
    int t  = bt & (T_-1);

    size_t base = ((size_t)bt*nh + n)*HD;
    float inv = exp2f(-(float)h * (13.287712379549449f / 64.0f));
    float ang = (float)t * inv;
    float sv, cv;
    sincosf(ang, &sv, &cv);
    float f = p[base + h], s2 = p[base + h + 64];
    float v1 = (f*cv - s2*sv) * scale;
    float v2 = (s2*cv + f*sv) * scale;
    if (is_q) {
        unsigned short h1, l1, h2, l2;
        split2h(v1, h1, l1); split2h(v2, h2, l2);
        ((unsigned short*)dhi)[base + h]      = h1;
        ((unsigned short*)g_qlo)[base + h]    = l1;
        ((unsigned short*)dhi)[base + h + 64] = h2;
        ((unsigned short*)g_qlo)[base + h + 64] = l2;
    } else {
        dhi[base + h]      = __float2half_rn(v1);
        dhi[base + h + 64] = __float2half_rn(v2);
    }
}

// ---------------- flash attention: reg-Q (hi/lo), K single fp16, dbl-buffered K & V ----------------
#define FROW 272
#define PROW 144
#define FK0  0
#define FK1  (64*FROW)          // 17408
#define FV0  (2*64*FROW)        // 34816
#define FV1  (3*64*FROW)        // 52224
#define FPP  (4*64*FROW)        // 69632
#define FLASH_SMEM (FPP + 64*PROW)  // 78848 -> 2 CTAs/SM

__global__ __launch_bounds__(128, 2) void flash_mma_kernel() {
    extern __shared__ char fsm[];
    uint32_t sb = smem_u32(fsm);
    int tid = threadIdx.x, w = tid >> 5, lane = tid & 31;
    int qt = blockIdx.x, head = blockIdx.y, b = blockIdx.z;
    int q0 = qt*64;
    int kvh = head >> 1;

    const __half* kh_b = g_khi + ((size_t)(b*T_))*NKV*HD + (size_t)kvh*HD;
    const __half* vh_b = g_vhi + ((size_t)(b*T_))*NKV*HD + (size_t)kvh*HD;

    int s_lo_raw = q0 - (WIN - 1);
    int s_lo = (s_lo_raw < 0 ? 0 : s_lo_raw) & ~63;
    int niter = ((q0 - s_lo) >> 6) + 1;

    uint32_t aoffQ = (uint32_t)((w*16 + (lane & 15))*FROW + (lane >> 4)*16);
    uint32_t brow  = (uint32_t)((lane & 7) + ((lane >> 4))*8);
    uint32_t bbyte = (uint32_t)(((lane >> 3) & 1)*16);
    uint32_t vrow  = (uint32_t)((lane & 7) + ((lane >> 3) & 1)*8);
    uint32_t vbyte = (uint32_t)((lane >> 4)*16);
    uint32_t aoffP = (uint32_t)((w*16 + (lane & 15))*PROW + (lane >> 4)*16);

    // ---- stage Q hi/lo through K0/K1 buffers, load to registers ----
    {
        const __half* qh = g_qhi + ((size_t)(b*T_ + q0)*NHQ + head)*HD;
        const __half* ql = g_qlo + ((size_t)(b*T_ + q0)*NHQ + head)*HD;
        #pragma unroll
        for (int i = 0; i < 8; i++) {
            int idx = i*128 + tid;
            int row = idx >> 4, c = idx & 15;
            CP_ASYNC16(sb + FK0 + row*FROW + c*16, qh + (size_t)row*(NHQ*HD) + c*8);
            CP_ASYNC16(sb + FK1 + row*FROW + c*16, ql + (size_t)row*(NHQ*HD) + c*8);
        }
        CP_COMMIT();
        CP_WAIT(0);
        __syncthreads();
    }
    uint32_t qh_r[8][4], ql_r[8][4];
    #pragma unroll
    for (int kstep = 0; kstep < 8; kstep++) {
        ldmx4(qh_r[kstep][0], qh_r[kstep][1], qh_r[kstep][2], qh_r[kstep][3],
              sb + FK0 + aoffQ + kstep*32);
        ldmx4(ql_r[kstep][0], ql_r[kstep][1], ql_r[kstep][2], ql_r[kstep][3],
              sb + FK1 + aoffQ + kstep*32);
    }
    __syncthreads();   // Q reads done before K loads overwrite

    // ---- issue K0 + V0 ----
    #pragma unroll
    for (int i = 0; i < 8; i++) {
        int idx = i*128 + tid;
        int row = idx >> 4, c = idx & 15;
        CP_ASYNC16(sb + FK0 + row*FROW + c*16, kh_b + (size_t)(s_lo+row)*(NKV*HD) + c*8);
        CP_ASYNC16(sb + FV0 + row*FROW + c*16, vh_b + (size_t)(s_lo+row)*(NKV*HD) + c*8);
    }
    CP_COMMIT();

    float m0 = -1e30f, m1 = -1e30f, l0 = 0.f, l1 = 0.f;
    float o[16][4];
    #pragma unroll
    for (int nt = 0; nt < 16; nt++)
        #pragma unroll
        for (int c = 0; c < 4; c++) o[nt][c] = 0.f;

    int q_r0 = q0 + w*16 + (lane >> 2);
    int q_r1 = q_r0 + 8;

    for (int it = 0; it < niter; it++) {
        int ks = s_lo + it*64;
        uint32_t kb  = sb + ((it & 1) ? FK1 : FK0);
        uint32_t vbf = sb + ((it & 1) ? FV1 : FV0);

        CP_WAIT(0);
        __syncthreads();

        if (it + 1 < niter) {
            uint32_t kbn = sb + (((it+1) & 1) ? FK1 : FK0);
            uint32_t vbn = sb + (((it+1) & 1) ? FV1 : FV0);
            int ksn = ks + 64;
            #pragma unroll
            for (int i = 0; i < 8; i++) {
                int idx = i*128 + tid;
                int row = idx >> 4, c = idx & 15;
                CP_ASYNC16(kbn + row*FROW + c*16, kh_b + (size_t)(ksn+row)*(NKV*HD) + c*8);
                CP_ASYNC16(vbn + row*FROW + c*16, vh_b + (size_t)(ksn+row)*(NKV*HD) + c*8);
            }
            CP_COMMIT();
        }

        // ---- S = Q @ K^T (Q hi+lo regs, K single) ----
        float sc[8][4];
        #pragma unroll
        for (int nt = 0; nt < 8; nt++)
            #pragma unroll
            for (int c = 0; c < 4; c++) sc[nt][c] = 0.f;

        #pragma unroll
        for (int kstep = 0; kstep < 8; kstep++) {
            uint32_t koff = kstep*32;
            uint32_t bh[2][2];
            #pragma unroll
            for (int ntp = 0; ntp < 4; ntp++) {
                uint32_t kaddr = kb + (brow + ntp*16)*FROW + bbyte + koff;
                ldmx4(bh[0][0], bh[0][1], bh[1][0], bh[1][1], kaddr);
                mma16816h(sc[2*ntp],   qh_r[kstep], bh[0]);
                mma16816h(sc[2*ntp+1], qh_r[kstep], bh[1]);
                mma16816h(sc[2*ntp],   ql_r[kstep], bh[0]);
                mma16816h(sc[2*ntp+1], ql_r[kstep], bh[1]);
            }
        }

        // ---- soft-cap, mask, online softmax ----
        float mx0 = -1e30f, mx1 = -1e30f;
        #pragma unroll
        for (int nt = 0; nt < 8; nt++) {
            #pragma unroll
            for (int c = 0; c < 4; c++) {
                float s = sc[nt][c];
                float u = s * 0.02f;
                float t2 = u*u;
                float pl = 1.f + t2*(-0.33333334f + t2*(0.13333333f + t2*(-0.05396825f + t2*0.02186949f)));
                float sp = s * pl;
                int col = ks + nt*8 + (lane & 3)*2 + (c & 1);
                int qq = (c < 2) ? q_r0 : q_r1;
                bool valid = (col <= qq) && (col > qq - WIN);
                sp = valid ? sp : -1e30f;
                sc[nt][c] = sp;
                if (c < 2) mx0 = fmaxf(mx0, sp); else mx1 = fmaxf(mx1, sp);
            }
        }
        mx0 = fmaxf(mx0, __shfl_xor_sync(0xffffffffu, mx0, 1));
        mx0 = fmaxf(mx0, __shfl_xor_sync(0xffffffffu, mx0, 2));
        mx1 = fmaxf(mx1, __shfl_xor_sync(0xffffffffu, mx1, 1));
        mx1 = fmaxf(mx1, __shfl_xor_sync(0xffffffffu, mx1, 2));

        float mn0 = fmaxf(fmaxf(m0, mx0), -60.f);
        float mn1 = fmaxf(fmaxf(m1, mx1), -60.f);
        float a0 = fastexp2((m0 - mn0)*LOG2E);
        float a1 = fastexp2((m1 - mn1)*LOG2E);
        m0 = mn0; m1 = mn1;

        float ps0 = 0.f, ps1 = 0.f;
        int prow0 = w*16 + (lane >> 2);
        uint32_t pcolb = (uint32_t)((lane & 3)*4);
        #pragma unroll
        for (int nt = 0; nt < 8; nt++) {
            float p0 = fastexp2((sc[nt][0] - mn0)*LOG2E);
            float p1 = fastexp2((sc[nt][1] - mn0)*LOG2E);
            float p2 = fastexp2((sc[nt][2] - mn1)*LOG2E);
            float p3 = fastexp2((sc[nt][3] - mn1)*LOG2E);
            ps0 += p0 + p1; ps1 += p2 + p3;
            __half2 lo2 = __floats2half2_rn(p0, p1);
            __half2 hi2 = __floats2half2_rn(p2, p3);
            *(uint32_t*)(fsm + FPP + prow0*PROW + nt*16 + pcolb)     = *(uint32_t*)&lo2;
            *(uint32_t*)(fsm + FPP + (prow0+8)*PROW + nt*16 + pcolb) = *(uint32_t*)&hi2;
        }
        ps0 += __shfl_xor_sync(0xffffffffu, ps0, 1);
        ps0 += __shfl_xor_sync(0xffffffffu, ps0, 2);
        ps1 += __shfl_xor_sync(0xffffffffu, ps1, 1);
        ps1 += __shfl_xor_sync(0xffffffffu, ps1, 2);
        l0 = l0*a0 + ps0;
        l1 = l1*a1 + ps1;
        #pragma unroll
        for (int nt = 0; nt < 16; nt++) {
            o[nt][0] *= a0; o[nt][1] *= a0;
            o[nt][2] *= a1; o[nt][3] *= a1;
        }
        __syncwarp();   // P stores visible within warp before ldmatrix

        // ---- O += P @ V ----
        #pragma unroll
        for (int kstep = 0; kstep < 4; kstep++) {
            uint32_t ap[4];
            ldmx4(ap[0], ap[1], ap[2], ap[3], sb + FPP + aoffP + kstep*32);
            #pragma unroll
            for (int nth = 0; nth < 8; nth++) {
                uint32_t vb[2][2];
                uint32_t va = vbf + (vrow + kstep*16)*FROW + nth*32 + vbyte;
                ldmx4t(vb[0][0], vb[0][1], vb[1][0], vb[1][1], va);
                mma16816h(o[2*nth],   ap, vb[0]);
                mma16816h(o[2*nth+1], ap, vb[1]);
            }
        }
    }

    // ---- normalize, store encoded (fp16) ----
    float li0 = 1.f / l0, li1 = 1.f / l1;
    size_t enc_r0 = ((size_t)(b*T_ + q_r0)*NHQ + head)*HD;
    size_t enc_r1 = ((size_t)(b*T_ + q_r1)*NHQ + head)*HD;
    int cb = (lane & 3)*2;
    #pragma unroll
    for (int nt = 0; nt < 16; nt++) {
        __half2 h0 = __floats2half2_rn(o[nt][0]*li0, o[nt][1]*li0);
        __half2 h1 = __floats2half2_rn(o[nt][2]*li1, o[nt][3]*li1);
        *(__half2*)(g_enchi + enc_r0 + nt*8 + cb) = h0;
        *(__half2*)(g_enchi + enc_r1 + nt*8 + cb) = h1;
    }
}

// ---------------------------------------------------------------------------
extern "C" void kernel_launch(void* const* d_in, const int* in_sizes, int n_in,
                              void* d_out, int out_size) {
    const float* x   = (const float*)d_in[0];
    const float* wq  = (const float*)d_in[3];
    const float* wkv = (const float*)d_in[4];
    const float* wo  = (const float*)d_in[5];
    float* out = (float*)d_out;

    cudaFuncSetAttribute(flash_mma_kernel, cudaFuncAttributeMaxDynamicSharedMemorySize, FLASH_SMEM);
    cudaFuncSetAttribute(gemm_mma_kernel,  cudaFuncAttributeMaxDynamicSharedMemorySize, GEMM_SMEM);

    convert_x_kernel<<<(M_*KDIM/4)/256, 256>>>(x);
    wqkv_transpose_kernel<<<dim3(4, 64, 32), dim3(32, 8)>>>(wq, wkv);
    wo_transpose_kernel<<<dim3(64, 64), dim3(32, 8)>>>(wo);

    gemm_mma_kernel<<<dim3(32, 32), 256, GEMM_SMEM>>>(nullptr, 0);   // QKV (+fused V fp16)

    rope_kernel<<<(M_*NHQ*64 + 255)/256, 256>>>(1);
    rope_kernel<<<(M_*NKV*64 + 255)/256, 256>>>(0);

    flash_mma_kernel<<<dim3(T_/64, NHQ, B_), 128, FLASH_SMEM>>>();

    gemm_mma_kernel<<<dim3(16, 32), 256, GEMM_SMEM>>>(out, 1);       // out proj
}

// round 15
// speedup vs baseline: 1.0982x; 1.0191x over previous
#include <cuda_runtime.h>
#include <cuda_bf16.h>
#include <cuda_fp16.h>
#include <math.h>
#include <stdint.h>
#include <stddef.h>

#define B_   2
#define T_   2048
#define NHQ  16
#define NKV  8
#define HD   128
#define FEAT 2048
#define WIN  1024
#define M_   (B_*T_)   // 4096
#define KDIM 2048
#define LOG2E 1.4426950408889634f

// ---------------- device scratch ----------------
__device__ __align__(128) float g_q  [(size_t)M_*NHQ*HD];
__device__ __align__(128) float g_k  [(size_t)M_*NKV*HD];

__device__ __align__(128) __half g_qhi[(size_t)M_*NHQ*HD];
__device__ __align__(128) __half g_qlo[(size_t)M_*NHQ*HD];
__device__ __align__(128) __half g_khi[(size_t)M_*NKV*HD];
__device__ __align__(128) __half g_vhi[(size_t)M_*NKV*HD];

__device__ __align__(128) __half g_xhi  [(size_t)M_*KDIM];
__device__ __align__(128) __half g_enchi[(size_t)M_*KDIM];
__device__ __align__(128) __half g_wallhi[(size_t)4096*KDIM];
__device__ __align__(128) __half g_wothi [(size_t)2048*KDIM];

// ---------------- helpers ----------------
__device__ __forceinline__ uint32_t smem_u32(const void* p) {
    uint32_t a;
    asm("{ .reg .u64 t; cvta.to.shared.u64 t, %1; cvt.u32.u64 %0, t; }" : "=r"(a) : "l"(p));
    return a;
}
__device__ __forceinline__ void ldmx4(uint32_t& r0, uint32_t& r1, uint32_t& r2, uint32_t& r3, uint32_t addr) {
    asm volatile("ldmatrix.sync.aligned.m8n8.x4.shared.b16 {%0,%1,%2,%3}, [%4];"
                 : "=r"(r0), "=r"(r1), "=r"(r2), "=r"(r3) : "r"(addr));
}
__device__ __forceinline__ void ldmx4t(uint32_t& r0, uint32_t& r1, uint32_t& r2, uint32_t& r3, uint32_t addr) {
    asm volatile("ldmatrix.sync.aligned.m8n8.x4.trans.shared.b16 {%0,%1,%2,%3}, [%4];"
                 : "=r"(r0), "=r"(r1), "=r"(r2), "=r"(r3) : "r"(addr));
}
__device__ __forceinline__ void mma16816h(float* c, const uint32_t* a, const uint32_t* b) {
    asm volatile("mma.sync.aligned.m16n8k16.row.col.f32.f16.f16.f32 "
                 "{%0,%1,%2,%3}, {%4,%5,%6,%7}, {%8,%9}, {%0,%1,%2,%3};"
                 : "+f"(c[0]), "+f"(c[1]), "+f"(c[2]), "+f"(c[3])
                 : "r"(a[0]), "r"(a[1]), "r"(a[2]), "r"(a[3]), "r"(b[0]), "r"(b[1]));
}
#define CP_ASYNC16(dst, src) \
    asm volatile("cp.async.cg.shared.global [%0], [%1], 16;" :: "r"(dst), "l"(src))
#define CP_COMMIT() asm volatile("cp.async.commit_group;" ::: "memory")
#define CP_WAIT(n)  asm volatile("cp.async.wait_group %0;" :: "n"(n) : "memory")

// ---------------- fp32 -> fp16 hi-lo split ----------------
__device__ __forceinline__ void split2h(float v, unsigned short& h, unsigned short& l) {
    __half hh = __float2half_rn(v);
    float r = v - __half2float(hh);
    __half hl = __float2half_rn(r);
    h = *reinterpret_cast<unsigned short*>(&hh);
    l = *reinterpret_cast<unsigned short*>(&hl);
}

__global__ void convert_x_kernel(const float* __restrict__ src) {
    int i = blockIdx.x*blockDim.x + threadIdx.x;
    float4 v = ((const float4*)src)[i];
    __half2 a = __floats2half2_rn(v.x, v.y);
    __half2 b = __floats2half2_rn(v.z, v.w);
    uint2 o = { *(uint32_t*)&a, *(uint32_t*)&b };
    ((uint2*)g_xhi)[i] = o;
}

__global__ void wqkv_transpose_kernel(const float* __restrict__ wq, const float* __restrict__ wkv) {
    __shared__ float t[32][33];
    int head = blockIdx.z;
    const float* src = (head < 16) ? (wq + (size_t)head*KDIM*HD)
                                   : (wkv + (size_t)(head-16)*KDIM*HD);
    int hd0 = blockIdx.x*32, k0 = blockIdx.y*32;
    int tx = threadIdx.x, ty = threadIdx.y;
    #pragma unroll
    for (int i = 0; i < 32; i += 8)
        t[ty+i][tx] = src[(size_t)(k0+ty+i)*HD + hd0 + tx];
    __syncthreads();
    #pragma unroll
    for (int i = 0; i < 32; i += 8) {
        int n = head*128 + hd0 + ty + i;
        g_wallhi[(size_t)n*KDIM + k0 + tx] = __float2half_rn(t[tx][ty+i]);
    }
}
__global__ void wo_transpose_kernel(const float* __restrict__ wo) {
    __shared__ float t[32][33];
    int c0 = blockIdx.x*32, r0 = blockIdx.y*32;
    int tx = threadIdx.x, ty = threadIdx.y;
    #pragma unroll
    for (int i = 0; i < 32; i += 8)
        t[ty+i][tx] = wo[(size_t)(r0+ty+i)*2048 + c0 + tx];
    __syncthreads();
    #pragma unroll
    for (int i = 0; i < 32; i += 8) {
        int n = c0 + ty + i;
        g_wothi[(size_t)n*KDIM + r0 + tx] = __float2half_rn(t[tx][ty+i]);
    }
}

// ---------------- mma.sync fp16 GEMM (frozen from R12) ----------------
#define KC      32
#define NKITER  (KDIM/KC)
#define AROWB   80
#define BUF_T   (128*AROWB)
#define STAGEB  (2*BUF_T)
#define GEMM_SMEM (3*STAGEB)    // 61440

__global__ __launch_bounds__(256, 2) void gemm_mma_kernel(float* __restrict__ outp, int mode) {
    extern __shared__ char smx[];
    uint32_t sbase = smem_u32(smx);
    int tid = threadIdx.x, wid = tid >> 5, lane = tid & 31;
    int bn = blockIdx.x, bm = blockIdx.y;
    int m0 = bm*128, n0 = bn*128;

    const __half *Ahi, *Bhi;
    if (mode == 0) { Ahi = g_xhi;   Bhi = g_wallhi; }
    else           { Ahi = g_enchi; Bhi = g_wothi;  }
    const __half* src0 = Ahi + (size_t)m0*KDIM;
    const __half* src2 = Bhi + (size_t)n0*KDIM;

    int wm = (wid & 3) * 32;
    int wn = (wid >> 2) * 64;

    uint32_t aoff = (uint32_t)((lane & 15)*AROWB + (lane >> 4)*16);
    int g = lane >> 3;
    uint32_t boff = (uint32_t)(((lane & 7) + (g >> 1)*8)*AROWB + (g & 1)*16);

    float acc[2][8][4];
    #pragma unroll
    for (int mt = 0; mt < 2; mt++)
        #pragma unroll
        for (int nt = 0; nt < 8; nt++)
            #pragma unroll
            for (int c = 0; c < 4; c++) acc[mt][nt][c] = 0.f;

    #define LOAD_STAGE(s, k0) do { \
        _Pragma("unroll") \
        for (int r = 0; r < 4; r++) { \
            const __half* sp_ = (r < 2) ? src0 : src2; \
            int within = (r & 1)*256 + tid; \
            int row = within >> 2, c16 = within & 3; \
            const void* sp = sp_ + (size_t)row*KDIM + (k0) + c16*8; \
            uint32_t dp = sbase + (s)*STAGEB + (r >> 1)*BUF_T + row*AROWB + c16*16; \
            CP_ASYNC16(dp, sp); \
        } \
        CP_COMMIT(); \
    } while (0)

    LOAD_STAGE(0, 0);
    LOAD_STAGE(1, KC);

    int p = 0, pn = 2;
    for (int i = 0; i < NKITER; i++) {
        if (i < NKITER-1) { CP_WAIT(1); } else { CP_WAIT(0); }
        __syncthreads();
        if (i + 2 < NKITER) {
            LOAD_STAGE(pn, (i+2)*KC);
            if (++pn == 3) pn = 0;
        }

        uint32_t saA = sbase + p*STAGEB;
        uint32_t saB = saA + BUF_T;
        if (++p == 3) p = 0;

        #pragma unroll
        for (int kstep = 0; kstep < 2; kstep++) {
            uint32_t koff = kstep*32;
            uint32_t ah[2][4], bb[8][2];
            #pragma unroll
            for (int mt = 0; mt < 2; mt++)
                ldmx4(ah[mt][0], ah[mt][1], ah[mt][2], ah[mt][3],
                      saA + aoff + (wm + mt*16)*AROWB + koff);
            #pragma unroll
            for (int ntp = 0; ntp < 4; ntp++)
                ldmx4(bb[2*ntp][0], bb[2*ntp][1], bb[2*ntp+1][0], bb[2*ntp+1][1],
                      saB + boff + (wn + ntp*16)*AROWB + koff);
            #pragma unroll
            for (int nt = 0; nt < 8; nt++)
                #pragma unroll
                for (int mt = 0; mt < 2; mt++)
                    mma16816h(acc[mt][nt], ah[mt], bb[nt]);
        }
    }

    int rbase_r = wm + (lane >> 2);
    int cloc = wn + (lane & 3)*2;

    if (mode == 0 && bn >= 24) {
        int coloff = (bn-24)*128;
        #pragma unroll
        for (int mt = 0; mt < 2; mt++) {
            #pragma unroll
            for (int nt = 0; nt < 8; nt++) {
                size_t r0 = (size_t)(m0 + rbase_r + mt*16)*(NKV*HD) + coloff + cloc + nt*8;
                size_t r1 = r0 + 8*(size_t)(NKV*HD);
                __half2 h0 = __floats2half2_rn(acc[mt][nt][0], acc[mt][nt][1]);
                __half2 h1 = __floats2half2_rn(acc[mt][nt][2], acc[mt][nt][3]);
                *(__half2*)(g_vhi + r0) = h0;
                *(__half2*)(g_vhi + r1) = h1;
            }
        }
    } else {
        float* dst; int ldd, coloff;
        if (mode == 0) {
            if (bn < 16) { dst = g_q; ldd = NHQ*HD; coloff = bn*128; }
            else         { dst = g_k; ldd = NKV*HD; coloff = (bn-16)*128; }
        } else { dst = outp; ldd = FEAT; coloff = bn*128; }
        int rbase = m0 + rbase_r;
        int cbase = coloff + cloc;
        #pragma unroll
        for (int mt = 0; mt < 2; mt++) {
            #pragma unroll
            for (int nt = 0; nt < 8; nt++) {
                size_t r0 = (size_t)(rbase + mt*16)*ldd + cbase + nt*8;
                *(float2*)&dst[r0]                 = make_float2(acc[mt][nt][0], acc[mt][nt][1]);
                *(float2*)&dst[r0 + 8*(size_t)ldd] = make_float2(acc[mt][nt][2], acc[mt][nt][3]);
            }
        }
    }
}

// ---------------- RoPE: Q -> fp16 hi/lo, K -> fp16 hi only ----------------
__global__ void rope_kernel(int is_q) {
    int nh = is_q ? NHQ : NKV;
    int idx = blockIdx.x*blockDim.x + threadIdx.x;
    if (idx >= M_*nh*64) return;
    const float* p = is_q ? g_q : g_k;
    __half* dhi = is_q ? g_qhi : g_khi;
    float scale = is_q ? 0.08838834764831845f : 1.0f;

    int h  = idx & 63;
    int n  = (idx >> 6) % nh;
    int bt = idx / (64*nh);
    int t  = bt & (T_-1);

    size_t base = ((size_t)bt*nh + n)*HD;
    float inv = exp2f(-(float)h * (13.287712379549449f / 64.0f));
    float ang = (float)t * inv;
    float sv, cv;
    sincosf(ang, &sv, &cv);
    float f = p[base + h], s2 = p[base + h + 64];
    float v1 = (f*cv - s2*sv) * scale;
    float v2 = (s2*cv + f*sv) * scale;
    if (is_q) {
        unsigned short h1, l1, h2, l2;
        split2h(v1, h1, l1); split2h(v2, h2, l2);
        ((unsigned short*)dhi)[base + h]      = h1;
        ((unsigned short*)g_qlo)[base + h]    = l1;
        ((unsigned short*)dhi)[base + h + 64] = h2;
        ((unsigned short*)g_qlo)[base + h + 64] = l2;
    } else {
        dhi[base + h]      = __float2half_rn(v1);
        dhi[base + h + 64] = __float2half_rn(v2);
    }
}

// ---------------- flash attention: fixed-m softmax, edge/interior split ----------------
#define FROW 272
#define PROW 144
#define FK0  0
#define FK1  (64*FROW)          // 17408
#define FV0  (2*64*FROW)        // 34816
#define FV1  (3*64*FROW)        // 52224
#define FPP  (4*64*FROW)        // 69632
#define FLASH_SMEM (FPP + 64*PROW)  // 78848 -> 2 CTAs/SM

// tanh-soft-cap poly coefficients, pre-scaled by LOG2E:
// x_log2 = s * (A0 + t2*(A1 + t2*(A2 + t2*(A3 + t2*A4)))), t2 = (0.02 s)^2
#define TA0 1.4426950408889634f
#define TA1 (-0.48089836f)
#define TA2 0.19235933f
#define TA3 (-0.07785618f)
#define TA4 0.03155130f

__global__ __launch_bounds__(128, 2) void flash_mma_kernel() {
    extern __shared__ char fsm[];
    uint32_t sb = smem_u32(fsm);
    int tid = threadIdx.x, w = tid >> 5, lane = tid & 31;
    int qt = blockIdx.x, head = blockIdx.y, b = blockIdx.z;
    int q0 = qt*64;
    int kvh = head >> 1;

    const __half* kh_b = g_khi + ((size_t)(b*T_))*NKV*HD + (size_t)kvh*HD;
    const __half* vh_b = g_vhi + ((size_t)(b*T_))*NKV*HD + (size_t)kvh*HD;

    int s_lo_raw = q0 - (WIN - 1);
    int s_lo = (s_lo_raw < 0 ? 0 : s_lo_raw) & ~63;
    int niter = ((q0 - s_lo) >> 6) + 1;

    uint32_t aoffQ = (uint32_t)((w*16 + (lane & 15))*FROW + (lane >> 4)*16);
    uint32_t brow  = (uint32_t)((lane & 7) + ((lane >> 4))*8);
    uint32_t bbyte = (uint32_t)(((lane >> 3) & 1)*16);
    uint32_t vrow  = (uint32_t)((lane & 7) + ((lane >> 3) & 1)*8);
    uint32_t vbyte = (uint32_t)((lane >> 4)*16);
    uint32_t aoffP = (uint32_t)((w*16 + (lane & 15))*PROW + (lane >> 4)*16);

    // ---- stage Q hi/lo through K0/K1 buffers, load to registers ----
    {
        const __half* qh = g_qhi + ((size_t)(b*T_ + q0)*NHQ + head)*HD;
        const __half* ql = g_qlo + ((size_t)(b*T_ + q0)*NHQ + head)*HD;
        #pragma unroll
        for (int i = 0; i < 8; i++) {
            int idx = i*128 + tid;
            int row = idx >> 4, c = idx & 15;
            CP_ASYNC16(sb + FK0 + row*FROW + c*16, qh + (size_t)row*(NHQ*HD) + c*8);
            CP_ASYNC16(sb + FK1 + row*FROW + c*16, ql + (size_t)row*(NHQ*HD) + c*8);
        }
        CP_COMMIT();
        CP_WAIT(0);
        __syncthreads();
    }
    uint32_t qh_r[8][4], ql_r[8][4];
    #pragma unroll
    for (int kstep = 0; kstep < 8; kstep++) {
        ldmx4(qh_r[kstep][0], qh_r[kstep][1], qh_r[kstep][2], qh_r[kstep][3],
              sb + FK0 + aoffQ + kstep*32);
        ldmx4(ql_r[kstep][0], ql_r[kstep][1], ql_r[kstep][2], ql_r[kstep][3],
              sb + FK1 + aoffQ + kstep*32);
    }
    __syncthreads();   // Q reads done before K loads overwrite

    // ---- issue K0 + V0 ----
    #pragma unroll
    for (int i = 0; i < 8; i++) {
        int idx = i*128 + tid;
        int row = idx >> 4, c = idx & 15;
        CP_ASYNC16(sb + FK0 + row*FROW + c*16, kh_b + (size_t)(s_lo+row)*(NKV*HD) + c*8);
        CP_ASYNC16(sb + FV0 + row*FROW + c*16, vh_b + (size_t)(s_lo+row)*(NKV*HD) + c*8);
    }
    CP_COMMIT();

    float l0 = 0.f, l1 = 0.f;
    float o[16][4];
    #pragma unroll
    for (int nt = 0; nt < 16; nt++)
        #pragma unroll
        for (int c = 0; c < 4; c++) o[nt][c] = 0.f;

    int q_r0 = q0 + w*16 + (lane >> 2);
    int q_r1 = q_r0 + 8;

    for (int it = 0; it < niter; it++) {
        int ks = s_lo + it*64;
        uint32_t kb  = sb + ((it & 1) ? FK1 : FK0);
        uint32_t vbf = sb + ((it & 1) ? FV1 : FV0);

        CP_WAIT(0);
        __syncthreads();

        if (it + 1 < niter) {
            uint32_t kbn = sb + (((it+1) & 1) ? FK1 : FK0);
            uint32_t vbn = sb + (((it+1) & 1) ? FV1 : FV0);
            int ksn = ks + 64;
            #pragma unroll
            for (int i = 0; i < 8; i++) {
                int idx = i*128 + tid;
                int row = idx >> 4, c = idx & 15;
                CP_ASYNC16(kbn + row*FROW + c*16, kh_b + (size_t)(ksn+row)*(NKV*HD) + c*8);
                CP_ASYNC16(vbn + row*FROW + c*16, vh_b + (size_t)(ksn+row)*(NKV*HD) + c*8);
            }
            CP_COMMIT();
        }

        // ---- S = Q @ K^T (Q hi+lo regs, K single) ----
        float sc[8][4];
        #pragma unroll
        for (int nt = 0; nt < 8; nt++)
            #pragma unroll
            for (int c = 0; c < 4; c++) sc[nt][c] = 0.f;

        #pragma unroll
        for (int kstep = 0; kstep < 8; kstep++) {
            uint32_t koff = kstep*32;
            uint32_t bh[2][2];
            #pragma unroll
            for (int ntp = 0; ntp < 4; ntp++) {
                uint32_t kaddr = kb + (brow + ntp*16)*FROW + bbyte + koff;
                ldmx4(bh[0][0], bh[0][1], bh[1][0], bh[1][1], kaddr);
                mma16816h(sc[2*ntp],   qh_r[kstep], bh[0]);
                mma16816h(sc[2*ntp+1], qh_r[kstep], bh[1]);
                mma16816h(sc[2*ntp],   ql_r[kstep], bh[0]);
                mma16816h(sc[2*ntp+1], ql_r[kstep], bh[1]);
            }
        }

        // ---- fixed-m softmax: p = exp(softcap(s)); mask only on edge tiles ----
        bool edge = (ks + 64 > q0) || (ks < q0 - 960);
        int prow0 = w*16 + (lane >> 2);
        uint32_t pcolb = (uint32_t)((lane & 3)*4);
        #pragma unroll
        for (int nt = 0; nt < 8; nt++) {
            float pv[4];
            #pragma unroll
            for (int c = 0; c < 4; c++) {
                float s = sc[nt][c];
                float u = s * 0.02f;
                float t2 = u*u;
                float pl = TA0 + t2*(TA1 + t2*(TA2 + t2*(TA3 + t2*TA4)));
                float x = s * pl;               // log2(p), p = exp(softcap(s))
                if (edge) {
                    int col = ks + nt*8 + (lane & 3)*2 + (c & 1);
                    int qq = (c < 2) ? q_r0 : q_r1;
                    bool valid = (col <= qq) && (col > qq - WIN);
                    x = valid ? x : -200.f;
                }
                x = fminf(fmaxf(x, -126.f), 15.f);   // fp16-safe range
                int ei = __float2int_rn(x);
                float f = x - (float)ei;
                float p = 1.f + f*(0.6931472f + f*(0.24022651f + f*(0.05550411f + f*(0.00961813f + f*0.00133336f))));
                pv[c] = p * __int_as_float((ei + 127) << 23);
            }
            l0 += pv[0] + pv[1];
            l1 += pv[2] + pv[3];
            __half2 lo2 = __floats2half2_rn(pv[0], pv[1]);
            __half2 hi2 = __floats2half2_rn(pv[2], pv[3]);
            *(uint32_t*)(fsm + FPP + prow0*PROW + nt*16 + pcolb)     = *(uint32_t*)&lo2;
            *(uint32_t*)(fsm + FPP + (prow0+8)*PROW + nt*16 + pcolb) = *(uint32_t*)&hi2;
        }
        __syncwarp();   // P stores visible within warp before ldmatrix

        // ---- O += P @ V ----
        #pragma unroll
        for (int kstep = 0; kstep < 4; kstep++) {
            uint32_t ap[4];
            ldmx4(ap[0], ap[1], ap[2], ap[3], sb + FPP + aoffP + kstep*32);
            #pragma unroll
            for (int nth = 0; nth < 8; nth++) {
                uint32_t vb[2][2];
                uint32_t va = vbf + (vrow + kstep*16)*FROW + nth*32 + vbyte;
                ldmx4t(vb[0][0], vb[0][1], vb[1][0], vb[1][1], va);
                mma16816h(o[2*nth],   ap, vb[0]);
                mma16816h(o[2*nth+1], ap, vb[1]);
            }
        }
    }

    // ---- single deferred l reduction ----
    l0 += __shfl_xor_sync(0xffffffffu, l0, 1);
    l0 += __shfl_xor_sync(0xffffffffu, l0, 2);
    l1 += __shfl_xor_sync(0xffffffffu, l1, 1);
    l1 += __shfl_xor_sync(0xffffffffu, l1, 2);

    // ---- normalize, store encoded (fp16) ----
    float li0 = 1.f / l0, li1 = 1.f / l1;
    size_t enc_r0 = ((size_t)(b*T_ + q_r0)*NHQ + head)*HD;
    size_t enc_r1 = ((size_t)(b*T_ + q_r1)*NHQ + head)*HD;
    int cb = (lane & 3)*2;
    #pragma unroll
    for (int nt = 0; nt < 16; nt++) {
        __half2 h0 = __floats2half2_rn(o[nt][0]*li0, o[nt][1]*li0);
        __half2 h1 = __floats2half2_rn(o[nt][2]*li1, o[nt][3]*li1);
        *(__half2*)(g_enchi + enc_r0 + nt*8 + cb) = h0;
        *(__half2*)(g_enchi + enc_r1 + nt*8 + cb) = h1;
    }
}

// ---------------------------------------------------------------------------
extern "C" void kernel_launch(void* const* d_in, const int* in_sizes, int n_in,
                              void* d_out, int out_size) {
    const float* x   = (const float*)d_in[0];
    const float* wq  = (const float*)d_in[3];
    const float* wkv = (const float*)d_in[4];
    const float* wo  = (const float*)d_in[5];
    float* out = (float*)d_out;

    cudaFuncSetAttribute(flash_mma_kernel, cudaFuncAttributeMaxDynamicSharedMemorySize, FLASH_SMEM);
    cudaFuncSetAttribute(gemm_mma_kernel,  cudaFuncAttributeMaxDynamicSharedMemorySize, GEMM_SMEM);

    convert_x_kernel<<<(M_*KDIM/4)/256, 256>>>(x);
    wqkv_transpose_kernel<<<dim3(4, 64, 32), dim3(32, 8)>>>(wq, wkv);
    wo_transpose_kernel<<<dim3(64, 64), dim3(32, 8)>>>(wo);

    gemm_mma_kernel<<<dim3(32, 32), 256, GEMM_SMEM>>>(nullptr, 0);   // QKV (+fused V fp16)

    rope_kernel<<<(M_*NHQ*64 + 255)/256, 256>>>(1);
    rope_kernel<<<(M_*NKV*64 + 255)/256, 256>>>(0);

    flash_mma_kernel<<<dim3(T_/64, NHQ, B_), 128, FLASH_SMEM>>>();

    gemm_mma_kernel<<<dim3(16, 32), 256, GEMM_SMEM>>>(out, 1);       // out proj
}

// round 16
// speedup vs baseline: 1.2455x; 1.1342x over previous
#include <cuda_runtime.h>
#include <cuda_bf16.h>
#include <cuda_fp16.h>
#include <math.h>
#include <stdint.h>
#include <stddef.h>

#define B_   2
#define T_   2048
#define NHQ  16
#define NKV  8
#define HD   128
#define FEAT 2048
#define WIN  1024
#define M_   (B_*T_)   // 4096
#define KDIM 2048
#define LOG2E 1.4426950408889634f

// ---------------- device scratch ----------------
__device__ __align__(128) float g_q  [(size_t)M_*NHQ*HD];
__device__ __align__(128) float g_k  [(size_t)M_*NKV*HD];

__device__ __align__(128) __half g_qhi[(size_t)M_*NHQ*HD];
__device__ __align__(128) __half g_khi[(size_t)M_*NKV*HD];
__device__ __align__(128) __half g_vhi[(size_t)M_*NKV*HD];

__device__ __align__(128) __half g_xhi  [(size_t)M_*KDIM];
__device__ __align__(128) __half g_enchi[(size_t)M_*KDIM];
__device__ __align__(128) __half g_wallhi[(size_t)4096*KDIM];
__device__ __align__(128) __half g_wothi [(size_t)2048*KDIM];

// ---------------- helpers ----------------
__device__ __forceinline__ uint32_t smem_u32(const void* p) {
    uint32_t a;
    asm("{ .reg .u64 t; cvta.to.shared.u64 t, %1; cvt.u32.u64 %0, t; }" : "=r"(a) : "l"(p));
    return a;
}
__device__ __forceinline__ void ldmx4(uint32_t& r0, uint32_t& r1, uint32_t& r2, uint32_t& r3, uint32_t addr) {
    asm volatile("ldmatrix.sync.aligned.m8n8.x4.shared.b16 {%0,%1,%2,%3}, [%4];"
                 : "=r"(r0), "=r"(r1), "=r"(r2), "=r"(r3) : "r"(addr));
}
__device__ __forceinline__ void ldmx4t(uint32_t& r0, uint32_t& r1, uint32_t& r2, uint32_t& r3, uint32_t addr) {
    asm volatile("ldmatrix.sync.aligned.m8n8.x4.trans.shared.b16 {%0,%1,%2,%3}, [%4];"
                 : "=r"(r0), "=r"(r1), "=r"(r2), "=r"(r3) : "r"(addr));
}
__device__ __forceinline__ void mma16816h(float* c, const uint32_t* a, const uint32_t* b) {
    asm volatile("mma.sync.aligned.m16n8k16.row.col.f32.f16.f16.f32 "
                 "{%0,%1,%2,%3}, {%4,%5,%6,%7}, {%8,%9}, {%0,%1,%2,%3};"
                 : "+f"(c[0]), "+f"(c[1]), "+f"(c[2]), "+f"(c[3])
                 : "r"(a[0]), "r"(a[1]), "r"(a[2]), "r"(a[3]), "r"(b[0]), "r"(b[1]));
}
#define CP_ASYNC16(dst, src) \
    asm volatile("cp.async.cg.shared.global [%0], [%1], 16;" :: "r"(dst), "l"(src))
#define CP_COMMIT() asm volatile("cp.async.commit_group;" ::: "memory")
#define CP_WAIT(n)  asm volatile("cp.async.wait_group %0;" :: "n"(n) : "memory")

__global__ void convert_x_kernel(const float* __restrict__ src) {
    int i = blockIdx.x*blockDim.x + threadIdx.x;
    float4 v = ((const float4*)src)[i];
    __half2 a = __floats2half2_rn(v.x, v.y);
    __half2 b = __floats2half2_rn(v.z, v.w);
    uint2 o = { *(uint32_t*)&a, *(uint32_t*)&b };
    ((uint2*)g_xhi)[i] = o;
}

__global__ void wqkv_transpose_kernel(const float* __restrict__ wq, const float* __restrict__ wkv) {
    __shared__ float t[32][33];
    int head = blockIdx.z;
    const float* src = (head < 16) ? (wq + (size_t)head*KDIM*HD)
                                   : (wkv + (size_t)(head-16)*KDIM*HD);
    int hd0 = blockIdx.x*32, k0 = blockIdx.y*32;
    int tx = threadIdx.x, ty = threadIdx.y;
    #pragma unroll
    for (int i = 0; i < 32; i += 8)
        t[ty+i][tx] = src[(size_t)(k0+ty+i)*HD + hd0 + tx];
    __syncthreads();
    #pragma unroll
    for (int i = 0; i < 32; i += 8) {
        int n = head*128 + hd0 + ty + i;
        g_wallhi[(size_t)n*KDIM + k0 + tx] = __float2half_rn(t[tx][ty+i]);
    }
}
__global__ void wo_transpose_kernel(const float* __restrict__ wo) {
    __shared__ float t[32][33];
    int c0 = blockIdx.x*32, r0 = blockIdx.y*32;
    int tx = threadIdx.x, ty = threadIdx.y;
    #pragma unroll
    for (int i = 0; i < 32; i += 8)
        t[ty+i][tx] = wo[(size_t)(r0+ty+i)*2048 + c0 + tx];
    __syncthreads();
    #pragma unroll
    for (int i = 0; i < 32; i += 8) {
        int n = c0 + ty + i;
        g_wothi[(size_t)n*KDIM + r0 + tx] = __float2half_rn(t[tx][ty+i]);
    }
}

// ---------------- mma.sync fp16 GEMM, 64x64 warp tiles, 4 warps ----------------
#define KC      32
#define NKITER  (KDIM/KC)
#define AROWB   80
#define BUF_T   (128*AROWB)
#define STAGEB  (2*BUF_T)
#define GEMM_SMEM (3*STAGEB)    // 61440

__global__ __launch_bounds__(128, 2) void gemm_mma_kernel(float* __restrict__ outp, int mode) {
    extern __shared__ char smx[];
    uint32_t sbase = smem_u32(smx);
    int tid = threadIdx.x, wid = tid >> 5, lane = tid & 31;
    int bn = blockIdx.x, bm = blockIdx.y;
    int m0 = bm*128, n0 = bn*128;

    const __half *Ahi, *Bhi;
    if (mode == 0) { Ahi = g_xhi;   Bhi = g_wallhi; }
    else           { Ahi = g_enchi; Bhi = g_wothi;  }
    const __half* src0 = Ahi + (size_t)m0*KDIM;
    const __half* src2 = Bhi + (size_t)n0*KDIM;

    int wm = (wid & 1) * 64;
    int wn = (wid >> 1) * 64;

    uint32_t aoff = (uint32_t)((lane & 15)*AROWB + (lane >> 4)*16);
    int g = lane >> 3;
    uint32_t boff = (uint32_t)(((lane & 7) + (g >> 1)*8)*AROWB + (g & 1)*16);

    float acc[4][8][4];
    #pragma unroll
    for (int mt = 0; mt < 4; mt++)
        #pragma unroll
        for (int nt = 0; nt < 8; nt++)
            #pragma unroll
            for (int c = 0; c < 4; c++) acc[mt][nt][c] = 0.f;

    // 128 threads: each tile (128x32 fp16 = 8KB = 512 x 16B), 4 chunks/thread/tile
    #define LOAD_STAGE(s, k0) do { \
        _Pragma("unroll") \
        for (int r = 0; r < 8; r++) { \
            const __half* sp_ = (r < 4) ? src0 : src2; \
            int within = (r & 3)*128 + tid; \
            int row = within >> 2, c16 = within & 3; \
            const void* sp = sp_ + (size_t)row*KDIM + (k0) + c16*8; \
            uint32_t dp = sbase + (s)*STAGEB + (r >> 2)*BUF_T + row*AROWB + c16*16; \
            CP_ASYNC16(dp, sp); \
        } \
        CP_COMMIT(); \
    } while (0)

    LOAD_STAGE(0, 0);
    LOAD_STAGE(1, KC);

    int p = 0, pn = 2;
    for (int i = 0; i < NKITER; i++) {
        if (i < NKITER-1) { CP_WAIT(1); } else { CP_WAIT(0); }
        __syncthreads();
        if (i + 2 < NKITER) {
            LOAD_STAGE(pn, (i+2)*KC);
            if (++pn == 3) pn = 0;
        }

        uint32_t saA = sbase + p*STAGEB;
        uint32_t saB = saA + BUF_T;
        if (++p == 3) p = 0;

        #pragma unroll
        for (int kstep = 0; kstep < 2; kstep++) {
            uint32_t koff = kstep*32;
            uint32_t ah[4][4], bb[8][2];
            #pragma unroll
            for (int mt = 0; mt < 4; mt++)
                ldmx4(ah[mt][0], ah[mt][1], ah[mt][2], ah[mt][3],
                      saA + aoff + (wm + mt*16)*AROWB + koff);
            #pragma unroll
            for (int ntp = 0; ntp < 4; ntp++)
                ldmx4(bb[2*ntp][0], bb[2*ntp][1], bb[2*ntp+1][0], bb[2*ntp+1][1],
                      saB + boff + (wn + ntp*16)*AROWB + koff);
            #pragma unroll
            for (int nt = 0; nt < 8; nt++)
                #pragma unroll
                for (int mt = 0; mt < 4; mt++)
                    mma16816h(acc[mt][nt], ah[mt], bb[nt]);
        }
    }

    int rbase_r = wm + (lane >> 2);
    int cloc = wn + (lane & 3)*2;

    if (mode == 0 && bn >= 24) {
        int coloff = (bn-24)*128;
        #pragma unroll
        for (int mt = 0; mt < 4; mt++) {
            #pragma unroll
            for (int nt = 0; nt < 8; nt++) {
                size_t r0 = (size_t)(m0 + rbase_r + mt*16)*(NKV*HD) + coloff + cloc + nt*8;
                size_t r1 = r0 + 8*(size_t)(NKV*HD);
                __half2 h0 = __floats2half2_rn(acc[mt][nt][0], acc[mt][nt][1]);
                __half2 h1 = __floats2half2_rn(acc[mt][nt][2], acc[mt][nt][3]);
                *(__half2*)(g_vhi + r0) = h0;
                *(__half2*)(g_vhi + r1) = h1;
            }
        }
    } else {
        float* dst; int ldd, coloff;
        if (mode == 0) {
            if (bn < 16) { dst = g_q; ldd = NHQ*HD; coloff = bn*128; }
            else         { dst = g_k; ldd = NKV*HD; coloff = (bn-16)*128; }
        } else { dst = outp; ldd = FEAT; coloff = bn*128; }
        int rbase = m0 + rbase_r;
        int cbase = coloff + cloc;
        #pragma unroll
        for (int mt = 0; mt < 4; mt++) {
            #pragma unroll
            for (int nt = 0; nt < 8; nt++) {
                size_t r0 = (size_t)(rbase + mt*16)*ldd + cbase + nt*8;
                *(float2*)&dst[r0]                 = make_float2(acc[mt][nt][0], acc[mt][nt][1]);
                *(float2*)&dst[r0 + 8*(size_t)ldd] = make_float2(acc[mt][nt][2], acc[mt][nt][3]);
            }
        }
    }
}

// ---------------- RoPE: Q and K -> single fp16 ----------------
__global__ void rope_kernel(int is_q) {
    int nh = is_q ? NHQ : NKV;
    int idx = blockIdx.x*blockDim.x + threadIdx.x;
    if (idx >= M_*nh*64) return;
    const float* p = is_q ? g_q : g_k;
    __half* dhi = is_q ? g_qhi : g_khi;
    float scale = is_q ? 0.08838834764831845f : 1.0f;

    int h  = idx & 63;
    int n  = (idx >> 6) % nh;
    int bt = idx / (64*nh);
    int t  = bt & (T_-1);

    size_t base = ((size_t)bt*nh + n)*HD;
    float inv = exp2f(-(float)h * (13.287712379549449f / 64.0f));
    float ang = (float)t * inv;
    float sv, cv;
    sincosf(ang, &sv, &cv);
    float f = p[base + h], s2 = p[base + h + 64];
    dhi[base + h]      = __float2half_rn((f*cv - s2*sv) * scale);
    dhi[base + h + 64] = __float2half_rn((s2*cv + f*sv) * scale);
}

// ---------------- flash attention: single-fp16 Q,K,V; fixed-m softmax ----------------
#define FROW 272
#define PROW 144
#define FK0  0
#define FK1  (64*FROW)          // 17408
#define FV0  (2*64*FROW)        // 34816
#define FV1  (3*64*FROW)        // 52224
#define FPP  (4*64*FROW)        // 69632
#define FLASH_SMEM (FPP + 64*PROW)  // 78848 -> 2 CTAs/SM

#define TA0 1.4426950408889634f
#define TA1 (-0.48089836f)
#define TA2 0.19235933f
#define TA3 (-0.07785618f)
#define TA4 0.03155130f

__global__ __launch_bounds__(128, 2) void flash_mma_kernel() {
    extern __shared__ char fsm[];
    uint32_t sb = smem_u32(fsm);
    int tid = threadIdx.x, w = tid >> 5, lane = tid & 31;
    int qt = blockIdx.x, head = blockIdx.y, b = blockIdx.z;
    int q0 = qt*64;
    int kvh = head >> 1;

    const __half* kh_b = g_khi + ((size_t)(b*T_))*NKV*HD + (size_t)kvh*HD;
    const __half* vh_b = g_vhi + ((size_t)(b*T_))*NKV*HD + (size_t)kvh*HD;

    int s_lo_raw = q0 - (WIN - 1);
    int s_lo = (s_lo_raw < 0 ? 0 : s_lo_raw) & ~63;
    int niter = ((q0 - s_lo) >> 6) + 1;

    uint32_t aoffQ = (uint32_t)((w*16 + (lane & 15))*FROW + (lane >> 4)*16);
    uint32_t brow  = (uint32_t)((lane & 7) + ((lane >> 4))*8);
    uint32_t bbyte = (uint32_t)(((lane >> 3) & 1)*16);
    uint32_t vrow  = (uint32_t)((lane & 7) + ((lane >> 3) & 1)*8);
    uint32_t vbyte = (uint32_t)((lane >> 4)*16);
    uint32_t aoffP = (uint32_t)((w*16 + (lane & 15))*PROW + (lane >> 4)*16);

    // ---- stage Q (single fp16) through K0 buffer, load to registers ----
    {
        const __half* qh = g_qhi + ((size_t)(b*T_ + q0)*NHQ + head)*HD;
        #pragma unroll
        for (int i = 0; i < 8; i++) {
            int idx = i*128 + tid;
            int row = idx >> 4, c = idx & 15;
            CP_ASYNC16(sb + FK0 + row*FROW + c*16, qh + (size_t)row*(NHQ*HD) + c*8);
        }
        CP_COMMIT();
        CP_WAIT(0);
        __syncthreads();
    }
    uint32_t qh_r[8][4];
    #pragma unroll
    for (int kstep = 0; kstep < 8; kstep++)
        ldmx4(qh_r[kstep][0], qh_r[kstep][1], qh_r[kstep][2], qh_r[kstep][3],
              sb + FK0 + aoffQ + kstep*32);
    __syncthreads();   // Q reads done before K loads overwrite

    // ---- issue K0 + V0 ----
    #pragma unroll
    for (int i = 0; i < 8; i++) {
        int idx = i*128 + tid;
        int row = idx >> 4, c = idx & 15;
        CP_ASYNC16(sb + FK0 + row*FROW + c*16, kh_b + (size_t)(s_lo+row)*(NKV*HD) + c*8);
        CP_ASYNC16(sb + FV0 + row*FROW + c*16, vh_b + (size_t)(s_lo+row)*(NKV*HD) + c*8);
    }
    CP_COMMIT();

    float l0 = 0.f, l1 = 0.f;
    float o[16][4];
    #pragma unroll
    for (int nt = 0; nt < 16; nt++)
        #pragma unroll
        for (int c = 0; c < 4; c++) o[nt][c] = 0.f;

    int q_r0 = q0 + w*16 + (lane >> 2);
    int q_r1 = q_r0 + 8;

    for (int it = 0; it < niter; it++) {
        int ks = s_lo + it*64;
        uint32_t kb  = sb + ((it & 1) ? FK1 : FK0);
        uint32_t vbf = sb + ((it & 1) ? FV1 : FV0);

        CP_WAIT(0);
        __syncthreads();

        if (it + 1 < niter) {
            uint32_t kbn = sb + (((it+1) & 1) ? FK1 : FK0);
            uint32_t vbn = sb + (((it+1) & 1) ? FV1 : FV0);
            int ksn = ks + 64;
            #pragma unroll
            for (int i = 0; i < 8; i++) {
                int idx = i*128 + tid;
                int row = idx >> 4, c = idx & 15;
                CP_ASYNC16(kbn + row*FROW + c*16, kh_b + (size_t)(ksn+row)*(NKV*HD) + c*8);
                CP_ASYNC16(vbn + row*FROW + c*16, vh_b + (size_t)(ksn+row)*(NKV*HD) + c*8);
            }
            CP_COMMIT();
        }

        // ---- S = Q @ K^T (single x single) ----
        float sc[8][4];
        #pragma unroll
        for (int nt = 0; nt < 8; nt++)
            #pragma unroll
            for (int c = 0; c < 4; c++) sc[nt][c] = 0.f;

        #pragma unroll
        for (int kstep = 0; kstep < 8; kstep++) {
            uint32_t koff = kstep*32;
            uint32_t bh[2][2];
            #pragma unroll
            for (int ntp = 0; ntp < 4; ntp++) {
                uint32_t kaddr = kb + (brow + ntp*16)*FROW + bbyte + koff;
                ldmx4(bh[0][0], bh[0][1], bh[1][0], bh[1][1], kaddr);
                mma16816h(sc[2*ntp],   qh_r[kstep], bh[0]);
                mma16816h(sc[2*ntp+1], qh_r[kstep], bh[1]);
            }
        }

        // ---- fixed-m softmax: p = exp(softcap(s)); mask only on edge tiles ----
        bool edge = (ks + 64 > q0) || (ks < q0 - 960);
        int prow0 = w*16 + (lane >> 2);
        uint32_t pcolb = (uint32_t)((lane & 3)*4);
        #pragma unroll
        for (int nt = 0; nt < 8; nt++) {
            float pv[4];
            #pragma unroll
            for (int c = 0; c < 4; c++) {
                float s = sc[nt][c];
                float u = s * 0.02f;
                float t2 = u*u;
                float pl = TA0 + t2*(TA1 + t2*(TA2 + t2*(TA3 + t2*TA4)));
                float x = s * pl;
                if (edge) {
                    int col = ks + nt*8 + (lane & 3)*2 + (c & 1);
                    int qq = (c < 2) ? q_r0 : q_r1;
                    bool valid = (col <= qq) && (col > qq - WIN);
                    x = valid ? x : -200.f;
                }
                x = fminf(fmaxf(x, -126.f), 15.f);
                int ei = __float2int_rn(x);
                float f = x - (float)ei;
                float p = 1.f + f*(0.6931472f + f*(0.24022651f + f*(0.05550411f + f*(0.00961813f + f*0.00133336f))));
                pv[c] = p * __int_as_float((ei + 127) << 23);
            }
            l0 += pv[0] + pv[1];
            l1 += pv[2] + pv[3];
            __half2 lo2 = __floats2half2_rn(pv[0], pv[1]);
            __half2 hi2 = __floats2half2_rn(pv[2], pv[3]);
            *(uint32_t*)(fsm + FPP + prow0*PROW + nt*16 + pcolb)     = *(uint32_t*)&lo2;
            *(uint32_t*)(fsm + FPP + (prow0+8)*PROW + nt*16 + pcolb) = *(uint32_t*)&hi2;
        }
        __syncwarp();

        // ---- O += P @ V ----
        #pragma unroll
        for (int kstep = 0; kstep < 4; kstep++) {
            uint32_t ap[4];
            ldmx4(ap[0], ap[1], ap[2], ap[3], sb + FPP + aoffP + kstep*32);
            #pragma unroll
            for (int nth = 0; nth < 8; nth++) {
                uint32_t vb[2][2];
                uint32_t va = vbf + (vrow + kstep*16)*FROW + nth*32 + vbyte;
                ldmx4t(vb[0][0], vb[0][1], vb[1][0], vb[1][1], va);
                mma16816h(o[2*nth],   ap, vb[0]);
                mma16816h(o[2*nth+1], ap, vb[1]);
            }
        }
    }

    l0 += __shfl_xor_sync(0xffffffffu, l0, 1);
    l0 += __shfl_xor_sync(0xffffffffu, l0, 2);
    l1 += __shfl_xor_sync(0xffffffffu, l1, 1);
    l1 += __shfl_xor_sync(0xffffffffu, l1, 2);

    float li0 = 1.f / l0, li1 = 1.f / l1;
    size_t enc_r0 = ((size_t)(b*T_ + q_r0)*NHQ + head)*HD;
    size_t enc_r1 = ((size_t)(b*T_ + q_r1)*NHQ + head)*HD;
    int cb = (lane & 3)*2;
    #pragma unroll
    for (int nt = 0; nt < 16; nt++) {
        __half2 h0 = __floats2half2_rn(o[nt][0]*li0, o[nt][1]*li0);
        __half2 h1 = __floats2half2_rn(o[nt][2]*li1, o[nt][3]*li1);
        *(__half2*)(g_enchi + enc_r0 + nt*8 + cb) = h0;
        *(__half2*)(g_enchi + enc_r1 + nt*8 + cb) = h1;
    }
}

// ---------------------------------------------------------------------------
extern "C" void kernel_launch(void* const* d_in, const int* in_sizes, int n_in,
                              void* d_out, int out_size) {
    const float* x   = (const float*)d_in[0];
    const float* wq  = (const float*)d_in[3];
    const float* wkv = (const float*)d_in[4];
    const float* wo  = (const float*)d_in[5];
    float* out = (float*)d_out;

    cudaFuncSetAttribute(flash_mma_kernel, cudaFuncAttributeMaxDynamicSharedMemorySize, FLASH_SMEM);
    cudaFuncSetAttribute(gemm_mma_kernel,  cudaFuncAttributeMaxDynamicSharedMemorySize, GEMM_SMEM);

    convert_x_kernel<<<(M_*KDIM/4)/256, 256>>>(x);
    wqkv_transpose_kernel<<<dim3(4, 64, 32), dim3(32, 8)>>>(wq, wkv);
    wo_transpose_kernel<<<dim3(64, 64), dim3(32, 8)>>>(wo);

    gemm_mma_kernel<<<dim3(32, 32), 128, GEMM_SMEM>>>(nullptr, 0);   // QKV (+fused V fp16)

    rope_kernel<<<(M_*NHQ*64 + 255)/256, 256>>>(1);
    rope_kernel<<<(M_*NKV*64 + 255)/256, 256>>>(0);

    flash_mma_kernel<<<dim3(T_/64, NHQ, B_), 128, FLASH_SMEM>>>();

    gemm_mma_kernel<<<dim3(16, 32), 128, GEMM_SMEM>>>(out, 1);       // out proj
}

// round 17
// speedup vs baseline: 1.2811x; 1.0286x over previous
#include <cuda_runtime.h>
#include <cuda_bf16.h>
#include <cuda_fp16.h>
#include <math.h>
#include <stdint.h>
#include <stddef.h>

#define B_   2
#define T_   2048
#define NHQ  16
#define NKV  8
#define HD   128
#define FEAT 2048
#define WIN  1024
#define M_   (B_*T_)   // 4096
#define KDIM 2048

// ---------------- device scratch ----------------
__device__ __align__(128) __half g_qhi[(size_t)M_*NHQ*HD];
__device__ __align__(128) __half g_khi[(size_t)M_*NKV*HD];
__device__ __align__(128) __half g_vhi[(size_t)M_*NKV*HD];

__device__ __align__(128) __half g_xhi  [(size_t)M_*KDIM];
__device__ __align__(128) __half g_enchi[(size_t)M_*KDIM];
__device__ __align__(128) __half g_wallhi[(size_t)4096*KDIM];
__device__ __align__(128) __half g_wothi [(size_t)2048*KDIM];

// ---------------- helpers ----------------
__device__ __forceinline__ uint32_t smem_u32(const void* p) {
    uint32_t a;
    asm("{ .reg .u64 t; cvta.to.shared.u64 t, %1; cvt.u32.u64 %0, t; }" : "=r"(a) : "l"(p));
    return a;
}
__device__ __forceinline__ void ldmx4(uint32_t& r0, uint32_t& r1, uint32_t& r2, uint32_t& r3, uint32_t addr) {
    asm volatile("ldmatrix.sync.aligned.m8n8.x4.shared.b16 {%0,%1,%2,%3}, [%4];"
                 : "=r"(r0), "=r"(r1), "=r"(r2), "=r"(r3) : "r"(addr));
}
__device__ __forceinline__ void ldmx4t(uint32_t& r0, uint32_t& r1, uint32_t& r2, uint32_t& r3, uint32_t addr) {
    asm volatile("ldmatrix.sync.aligned.m8n8.x4.trans.shared.b16 {%0,%1,%2,%3}, [%4];"
                 : "=r"(r0), "=r"(r1), "=r"(r2), "=r"(r3) : "r"(addr));
}
__device__ __forceinline__ void mma16816h(float* c, const uint32_t* a, const uint32_t* b) {
    asm volatile("mma.sync.aligned.m16n8k16.row.col.f32.f16.f16.f32 "
                 "{%0,%1,%2,%3}, {%4,%5,%6,%7}, {%8,%9}, {%0,%1,%2,%3};"
                 : "+f"(c[0]), "+f"(c[1]), "+f"(c[2]), "+f"(c[3])
                 : "r"(a[0]), "r"(a[1]), "r"(a[2]), "r"(a[3]), "r"(b[0]), "r"(b[1]));
}
__device__ __forceinline__ float ex2f(float x) {
    float r;
    asm("ex2.approx.f32 %0, %1;" : "=f"(r) : "f"(x));
    return r;
}
#define CP_ASYNC16(dst, src) \
    asm volatile("cp.async.cg.shared.global [%0], [%1], 16;" :: "r"(dst), "l"(src))
#define CP_COMMIT() asm volatile("cp.async.commit_group;" ::: "memory")
#define CP_WAIT(n)  asm volatile("cp.async.wait_group %0;" :: "n"(n) : "memory")

__global__ void convert_x_kernel(const float* __restrict__ src) {
    int i = blockIdx.x*blockDim.x + threadIdx.x;
    float4 v = ((const float4*)src)[i];
    __half2 a = __floats2half2_rn(v.x, v.y);
    __half2 b = __floats2half2_rn(v.z, v.w);
    uint2 o = { *(uint32_t*)&a, *(uint32_t*)&b };
    ((uint2*)g_xhi)[i] = o;
}

__global__ void wqkv_transpose_kernel(const float* __restrict__ wq, const float* __restrict__ wkv) {
    __shared__ float t[32][33];
    int head = blockIdx.z;
    const float* src = (head < 16) ? (wq + (size_t)head*KDIM*HD)
                                   : (wkv + (size_t)(head-16)*KDIM*HD);
    int hd0 = blockIdx.x*32, k0 = blockIdx.y*32;
    int tx = threadIdx.x, ty = threadIdx.y;
    #pragma unroll
    for (int i = 0; i < 32; i += 8)
        t[ty+i][tx] = src[(size_t)(k0+ty+i)*HD + hd0 + tx];
    __syncthreads();
    #pragma unroll
    for (int i = 0; i < 32; i += 8) {
        int n = head*128 + hd0 + ty + i;
        g_wallhi[(size_t)n*KDIM + k0 + tx] = __float2half_rn(t[tx][ty+i]);
    }
}
__global__ void wo_transpose_kernel(const float* __restrict__ wo) {
    __shared__ float t[32][33];
    int c0 = blockIdx.x*32, r0 = blockIdx.y*32;
    int tx = threadIdx.x, ty = threadIdx.y;
    #pragma unroll
    for (int i = 0; i < 32; i += 8)
        t[ty+i][tx] = wo[(size_t)(r0+ty+i)*2048 + c0 + tx];
    __syncthreads();
    #pragma unroll
    for (int i = 0; i < 32; i += 8) {
        int n = c0 + ty + i;
        g_wothi[(size_t)n*KDIM + r0 + tx] = __float2half_rn(t[tx][ty+i]);
    }
}

// ---------------- mma.sync fp16 GEMM, 64x64 warp tiles, 4 warps ----------------
#define KC      32
#define NKITER  (KDIM/KC)
#define AROWB   80
#define BUF_T   (128*AROWB)
#define STAGEB  (2*BUF_T)
#define GEMM_SMEM (3*STAGEB)    // 61440

__global__ __launch_bounds__(128, 2) void gemm_mma_kernel(float* __restrict__ outp, int mode) {
    extern __shared__ char smx[];
    uint32_t sbase = smem_u32(smx);
    int tid = threadIdx.x, wid = tid >> 5, lane = tid & 31;
    int bn = blockIdx.x, bm = blockIdx.y;
    int m0 = bm*128, n0 = bn*128;

    const __half *Ahi, *Bhi;
    if (mode == 0) { Ahi = g_xhi;   Bhi = g_wallhi; }
    else           { Ahi = g_enchi; Bhi = g_wothi;  }
    const __half* src0 = Ahi + (size_t)m0*KDIM;
    const __half* src2 = Bhi + (size_t)n0*KDIM;

    int wm = (wid & 1) * 64;
    int wn = (wid >> 1) * 64;

    uint32_t aoff = (uint32_t)((lane & 15)*AROWB + (lane >> 4)*16);
    int g = lane >> 3;
    uint32_t boff = (uint32_t)(((lane & 7) + (g >> 1)*8)*AROWB + (g & 1)*16);

    float acc[4][8][4];
    #pragma unroll
    for (int mt = 0; mt < 4; mt++)
        #pragma unroll
        for (int nt = 0; nt < 8; nt++)
            #pragma unroll
            for (int c = 0; c < 4; c++) acc[mt][nt][c] = 0.f;

    #define LOAD_STAGE(s, k0) do { \
        _Pragma("unroll") \
        for (int r = 0; r < 8; r++) { \
            const __half* sp_ = (r < 4) ? src0 : src2; \
            int within = (r & 3)*128 + tid; \
            int row = within >> 2, c16 = within & 3; \
            const void* sp = sp_ + (size_t)row*KDIM + (k0) + c16*8; \
            uint32_t dp = sbase + (s)*STAGEB + (r >> 2)*BUF_T + row*AROWB + c16*16; \
            CP_ASYNC16(dp, sp); \
        } \
        CP_COMMIT(); \
    } while (0)

    LOAD_STAGE(0, 0);
    LOAD_STAGE(1, KC);

    int p = 0, pn = 2;
    for (int i = 0; i < NKITER; i++) {
        if (i < NKITER-1) { CP_WAIT(1); } else { CP_WAIT(0); }
        __syncthreads();
        if (i + 2 < NKITER) {
            LOAD_STAGE(pn, (i+2)*KC);
            if (++pn == 3) pn = 0;
        }

        uint32_t saA = sbase + p*STAGEB;
        uint32_t saB = saA + BUF_T;
        if (++p == 3) p = 0;

        #pragma unroll
        for (int kstep = 0; kstep < 2; kstep++) {
            uint32_t koff = kstep*32;
            uint32_t ah[4][4], bb[8][2];
            #pragma unroll
            for (int mt = 0; mt < 4; mt++)
                ldmx4(ah[mt][0], ah[mt][1], ah[mt][2], ah[mt][3],
                      saA + aoff + (wm + mt*16)*AROWB + koff);
            #pragma unroll
            for (int ntp = 0; ntp < 4; ntp++)
                ldmx4(bb[2*ntp][0], bb[2*ntp][1], bb[2*ntp+1][0], bb[2*ntp+1][1],
                      saB + boff + (wn + ntp*16)*AROWB + koff);
            #pragma unroll
            for (int nt = 0; nt < 8; nt++)
                #pragma unroll
                for (int mt = 0; mt < 4; mt++)
                    mma16816h(acc[mt][nt], ah[mt], bb[nt]);
        }
    }

    int rbase_r = wm + (lane >> 2);
    int cloc = wn + (lane & 3)*2;

    if (mode == 0) {
        // all QKV outputs written as fp16 (Q/K unrotated; rope rotates in place)
        __half* hdst; int ldd, coloff;
        if (bn < 16)      { hdst = g_qhi; ldd = NHQ*HD; coloff = bn*128; }
        else if (bn < 24) { hdst = g_khi; ldd = NKV*HD; coloff = (bn-16)*128; }
        else              { hdst = g_vhi; ldd = NKV*HD; coloff = (bn-24)*128; }
        #pragma unroll
        for (int mt = 0; mt < 4; mt++) {
            #pragma unroll
            for (int nt = 0; nt < 8; nt++) {
                size_t r0 = (size_t)(m0 + rbase_r + mt*16)*ldd + coloff + cloc + nt*8;
                size_t r1 = r0 + 8*(size_t)ldd;
                __half2 h0 = __floats2half2_rn(acc[mt][nt][0], acc[mt][nt][1]);
                __half2 h1 = __floats2half2_rn(acc[mt][nt][2], acc[mt][nt][3]);
                *(__half2*)(hdst + r0) = h0;
                *(__half2*)(hdst + r1) = h1;
            }
        }
    } else {
        float* dst = outp;
        int ldd = FEAT, coloff = bn*128;
        int rbase = m0 + rbase_r;
        int cbase = coloff + cloc;
        #pragma unroll
        for (int mt = 0; mt < 4; mt++) {
            #pragma unroll
            for (int nt = 0; nt < 8; nt++) {
                size_t r0 = (size_t)(rbase + mt*16)*ldd + cbase + nt*8;
                *(float2*)&dst[r0]                 = make_float2(acc[mt][nt][0], acc[mt][nt][1]);
                *(float2*)&dst[r0 + 8*(size_t)ldd] = make_float2(acc[mt][nt][2], acc[mt][nt][3]);
            }
        }
    }
}

// ---------------- RoPE in place on fp16 Q/K ----------------
__global__ void rope_kernel(int is_q) {
    int nh = is_q ? NHQ : NKV;
    int idx = blockIdx.x*blockDim.x + threadIdx.x;
    if (idx >= M_*nh*64) return;
    __half* d = is_q ? g_qhi : g_khi;
    float scale = is_q ? 0.08838834764831845f : 1.0f;

    int h  = idx & 63;
    int n  = (idx >> 6) % nh;
    int bt = idx / (64*nh);
    int t  = bt & (T_-1);

    size_t base = ((size_t)bt*nh + n)*HD;
    float inv = exp2f(-(float)h * (13.287712379549449f / 64.0f));
    float ang = (float)t * inv;
    float sv, cv;
    sincosf(ang, &sv, &cv);
    float f = __half2float(d[base + h]), s2 = __half2float(d[base + h + 64]);
    d[base + h]      = __float2half_rn((f*cv - s2*sv) * scale);
    d[base + h + 64] = __float2half_rn((s2*cv + f*sv) * scale);
}

// ---------------- flash attention: fixed-m softmax with MUFU ex2 ----------------
#define FROW 272
#define PROW 144
#define FK0  0
#define FK1  (64*FROW)          // 17408
#define FV0  (2*64*FROW)        // 34816
#define FV1  (3*64*FROW)        // 52224
#define FPP  (4*64*FROW)        // 69632
#define FLASH_SMEM (FPP + 64*PROW)  // 78848 -> 2 CTAs/SM

#define TA0 1.4426950408889634f
#define TA1 (-0.48089836f)
#define TA2 0.19235933f
#define TA3 (-0.07785618f)
#define TA4 0.03155130f

__global__ __launch_bounds__(128, 2) void flash_mma_kernel() {
    extern __shared__ char fsm[];
    uint32_t sb = smem_u32(fsm);
    int tid = threadIdx.x, w = tid >> 5, lane = tid & 31;
    int qt = blockIdx.x, head = blockIdx.y, b = blockIdx.z;
    int q0 = qt*64;
    int kvh = head >> 1;

    const __half* kh_b = g_khi + ((size_t)(b*T_))*NKV*HD + (size_t)kvh*HD;
    const __half* vh_b = g_vhi + ((size_t)(b*T_))*NKV*HD + (size_t)kvh*HD;

    int s_lo_raw = q0 - (WIN - 1);
    int s_lo = (s_lo_raw < 0 ? 0 : s_lo_raw) & ~63;
    int niter = ((q0 - s_lo) >> 6) + 1;

    uint32_t aoffQ = (uint32_t)((w*16 + (lane & 15))*FROW + (lane >> 4)*16);
    uint32_t brow  = (uint32_t)((lane & 7) + ((lane >> 4))*8);
    uint32_t bbyte = (uint32_t)(((lane >> 3) & 1)*16);
    uint32_t vrow  = (uint32_t)((lane & 7) + ((lane >> 3) & 1)*8);
    uint32_t vbyte = (uint32_t)((lane >> 4)*16);
    uint32_t aoffP = (uint32_t)((w*16 + (lane & 15))*PROW + (lane >> 4)*16);

    // ---- stage Q through K0 buffer, load to registers ----
    {
        const __half* qh = g_qhi + ((size_t)(b*T_ + q0)*NHQ + head)*HD;
        #pragma unroll
        for (int i = 0; i < 8; i++) {
            int idx = i*128 + tid;
            int row = idx >> 4, c = idx & 15;
            CP_ASYNC16(sb + FK0 + row*FROW + c*16, qh + (size_t)row*(NHQ*HD) + c*8);
        }
        CP_COMMIT();
        CP_WAIT(0);
        __syncthreads();
    }
    uint32_t qh_r[8][4];
    #pragma unroll
    for (int kstep = 0; kstep < 8; kstep++)
        ldmx4(qh_r[kstep][0], qh_r[kstep][1], qh_r[kstep][2], qh_r[kstep][3],
              sb + FK0 + aoffQ + kstep*32);
    __syncthreads();

    // ---- issue K0 + V0 ----
    #pragma unroll
    for (int i = 0; i < 8; i++) {
        int idx = i*128 + tid;
        int row = idx >> 4, c = idx & 15;
        CP_ASYNC16(sb + FK0 + row*FROW + c*16, kh_b + (size_t)(s_lo+row)*(NKV*HD) + c*8);
        CP_ASYNC16(sb + FV0 + row*FROW + c*16, vh_b + (size_t)(s_lo+row)*(NKV*HD) + c*8);
    }
    CP_COMMIT();

    float l0 = 0.f, l1 = 0.f;
    float o[16][4];
    #pragma unroll
    for (int nt = 0; nt < 16; nt++)
        #pragma unroll
        for (int c = 0; c < 4; c++) o[nt][c] = 0.f;

    int q_r0 = q0 + w*16 + (lane >> 2);
    int q_r1 = q_r0 + 8;

    for (int it = 0; it < niter; it++) {
        int ks = s_lo + it*64;
        uint32_t kb  = sb + ((it & 1) ? FK1 : FK0);
        uint32_t vbf = sb + ((it & 1) ? FV1 : FV0);

        CP_WAIT(0);
        __syncthreads();

        if (it + 1 < niter) {
            uint32_t kbn = sb + (((it+1) & 1) ? FK1 : FK0);
            uint32_t vbn = sb + (((it+1) & 1) ? FV1 : FV0);
            int ksn = ks + 64;
            #pragma unroll
            for (int i = 0; i < 8; i++) {
                int idx = i*128 + tid;
                int row = idx >> 4, c = idx & 15;
                CP_ASYNC16(kbn + row*FROW + c*16, kh_b + (size_t)(ksn+row)*(NKV*HD) + c*8);
                CP_ASYNC16(vbn + row*FROW + c*16, vh_b + (size_t)(ksn+row)*(NKV*HD) + c*8);
            }
            CP_COMMIT();
        }

        // ---- S = Q @ K^T ----
        float sc[8][4];
        #pragma unroll
        for (int nt = 0; nt < 8; nt++)
            #pragma unroll
            for (int c = 0; c < 4; c++) sc[nt][c] = 0.f;

        #pragma unroll
        for (int kstep = 0; kstep < 8; kstep++) {
            uint32_t koff = kstep*32;
            uint32_t bh[2][2];
            #pragma unroll
            for (int ntp = 0; ntp < 4; ntp++) {
                uint32_t kaddr = kb + (brow + ntp*16)*FROW + bbyte + koff;
                ldmx4(bh[0][0], bh[0][1], bh[1][0], bh[1][1], kaddr);
                mma16816h(sc[2*ntp],   qh_r[kstep], bh[0]);
                mma16816h(sc[2*ntp+1], qh_r[kstep], bh[1]);
            }
        }

        // ---- fixed-m softmax with MUFU ex2 ----
        bool edge = (ks + 64 > q0) || (ks < q0 - 960);
        int prow0 = w*16 + (lane >> 2);
        uint32_t pcolb = (uint32_t)((lane & 3)*4);
        #pragma unroll
        for (int nt = 0; nt < 8; nt++) {
            float pv[4];
            #pragma unroll
            for (int c = 0; c < 4; c++) {
                float s = sc[nt][c];
                float u = s * 0.02f;
                float t2 = u*u;
                float pl = TA0 + t2*(TA1 + t2*(TA2 + t2*(TA3 + t2*TA4)));
                float x = s * pl;              // log2(p)
                if (edge) {
                    int col = ks + nt*8 + (lane & 3)*2 + (c & 1);
                    int qq = (c < 2) ? q_r0 : q_r1;
                    bool valid = (col <= qq) && (col > qq - WIN);
                    x = valid ? x : -200.f;
                }
                x = fminf(x, 15.f);            // fp16-safe upper clamp
                pv[c] = ex2f(x);
            }
            l0 += pv[0] + pv[1];
            l1 += pv[2] + pv[3];
            __half2 lo2 = __floats2half2_rn(pv[0], pv[1]);
            __half2 hi2 = __floats2half2_rn(pv[2], pv[3]);
            *(uint32_t*)(fsm + FPP + prow0*PROW + nt*16 + pcolb)     = *(uint32_t*)&lo2;
            *(uint32_t*)(fsm + FPP + (prow0+8)*PROW + nt*16 + pcolb) = *(uint32_t*)&hi2;
        }
        __syncwarp();

        // ---- O += P @ V ----
        #pragma unroll
        for (int kstep = 0; kstep < 4; kstep++) {
            uint32_t ap[4];
            ldmx4(ap[0], ap[1], ap[2], ap[3], sb + FPP + aoffP + kstep*32);
            #pragma unroll
            for (int nth = 0; nth < 8; nth++) {
                uint32_t vb[2][2];
                uint32_t va = vbf + (vrow + kstep*16)*FROW + nth*32 + vbyte;
                ldmx4t(vb[0][0], vb[0][1], vb[1][0], vb[1][1], va);
                mma16816h(o[2*nth],   ap, vb[0]);
                mma16816h(o[2*nth+1], ap, vb[1]);
            }
        }
    }

    l0 += __shfl_xor_sync(0xffffffffu, l0, 1);
    l0 += __shfl_xor_sync(0xffffffffu, l0, 2);
    l1 += __shfl_xor_sync(0xffffffffu, l1, 1);
    l1 += __shfl_xor_sync(0xffffffffu, l1, 2);

    float li0 = 1.f / l0, li1 = 1.f / l1;
    size_t enc_r0 = ((size_t)(b*T_ + q_r0)*NHQ + head)*HD;
    size_t enc_r1 = ((size_t)(b*T_ + q_r1)*NHQ + head)*HD;
    int cb = (lane & 3)*2;
    #pragma unroll
    for (int nt = 0; nt < 16; nt++) {
        __half2 h0 = __floats2half2_rn(o[nt][0]*li0, o[nt][1]*li0);
        __half2 h1 = __floats2half2_rn(o[nt][2]*li1, o[nt][3]*li1);
        *(__half2*)(g_enchi + enc_r0 + nt*8 + cb) = h0;
        *(__half2*)(g_enchi + enc_r1 + nt*8 + cb) = h1;
    }
}

// ---------------------------------------------------------------------------
extern "C" void kernel_launch(void* const* d_in, const int* in_sizes, int n_in,
                              void* d_out, int out_size) {
    const float* x   = (const float*)d_in[0];
    const float* wq  = (const float*)d_in[3];
    const float* wkv = (const float*)d_in[4];
    const float* wo  = (const float*)d_in[5];
    float* out = (float*)d_out;

    cudaFuncSetAttribute(flash_mma_kernel, cudaFuncAttributeMaxDynamicSharedMemorySize, FLASH_SMEM);
    cudaFuncSetAttribute(gemm_mma_kernel,  cudaFuncAttributeMaxDynamicSharedMemorySize, GEMM_SMEM);

    convert_x_kernel<<<(M_*KDIM/4)/256, 256>>>(x);
    wqkv_transpose_kernel<<<dim3(4, 64, 32), dim3(32, 8)>>>(wq, wkv);
    wo_transpose_kernel<<<dim3(64, 64), dim3(32, 8)>>>(wo);

    gemm_mma_kernel<<<dim3(32, 32), 128, GEMM_SMEM>>>(nullptr, 0);   // QKV (fp16 epilogue)

    rope_kernel<<<(M_*NHQ*64 + 255)/256, 256>>>(1);
    rope_kernel<<<(M_*NKV*64 + 255)/256, 256>>>(0);

    flash_mma_kernel<<<dim3(T_/64, NHQ, B_), 128, FLASH_SMEM>>>();

    gemm_mma_kernel<<<dim3(16, 32), 128, GEMM_SMEM>>>(out, 1);       // out proj
}